// round 1
// baseline (speedup 1.0000x reference)
#include <cuda_runtime.h>
#include <math.h>

// sLSTM cell fused kernel (fp32 baseline).
// gates = x @ Wx^T + h @ Wh^T + b   ->  [B, 4H]
// then exponential-gate elementwise epilogue.
//
// B=16384, IN=1024, H=1024.
// Tiling: each block computes BM=128 batch rows x BN=32 hidden cols,
// for ALL 4 gates (logical N tile = 128, gate-interleaved: lc = j*4 + gate).

#define BATCH 16384
#define HDIM  1024
#define BM 128
#define BN 32
#define BK 16
#define LN 128  // 4 * BN, gate-interleaved

__global__ __launch_bounds__(256, 2)
void slstm_fused_kernel(
    const float* __restrict__ x,   // [B, IN]
    const float* __restrict__ h,   // [B, H]
    const float* __restrict__ c,   // [B, H]
    const float* __restrict__ n,   // [B, H]
    const float* __restrict__ m,   // [B, H]
    const float* __restrict__ Wx,  // [4H, IN]
    const float* __restrict__ Wh,  // [4H, H]
    const float* __restrict__ bias,// [4H]
    float* __restrict__ out)       // [4, B, H] as (h_new, c_new, n_new, m_new)
{
    __shared__ float As[BK][BM + 4];
    __shared__ float Ws[BK][LN + 4];

    const int bj = blockIdx.x;   // 0..H/BN-1
    const int bb = blockIdx.y;   // 0..B/BM-1
    const int t  = threadIdx.x;  // 0..255
    const int tx = t & 15;       // 16 col-groups
    const int ty = t >> 4;       // 16 row-groups

    float acc[8][8];
    #pragma unroll
    for (int i = 0; i < 8; i++)
        #pragma unroll
        for (int j = 0; j < 8; j++)
            acc[i][j] = 0.0f;

    // Precompute load indices: q = pass*256 + t; l = q>>2 (tile row), c4 = q&3 (float4 col)
    // A tile row l -> global batch row bb*BM + l
    // W tile logical row l -> gate = l&3, j = l>>2 -> weight row gate*HDIM + bj*BN + j
    const int l0 = t >> 2;
    const int c4 = t & 3;
    const int arow0 = bb * BM + l0;
    const int arow1 = arow0 + 64;           // pass 1: q += 256 -> l += 64
    const int g0 = l0 & 3, j0 = l0 >> 2;
    const int l1 = l0 + 64;
    const int g1 = l1 & 3, j1 = l1 >> 2;
    const int wrow0 = g0 * HDIM + bj * BN + j0;
    const int wrow1 = g1 * HDIM + bj * BN + j1;

    for (int kk = 0; kk < 2048; kk += BK) {
        const float* Aptr;
        const float* Wptr;
        int kcol;
        if (kk < 1024) { Aptr = x; Wptr = Wx; kcol = kk; }
        else           { Aptr = h; Wptr = Wh; kcol = kk - 1024; }

        // --- load A tile: 128 rows x 16 cols ---
        {
            float4 av0 = *(const float4*)(Aptr + (size_t)arow0 * 1024 + kcol + c4 * 4);
            float4 av1 = *(const float4*)(Aptr + (size_t)arow1 * 1024 + kcol + c4 * 4);
            As[c4 * 4 + 0][l0] = av0.x;
            As[c4 * 4 + 1][l0] = av0.y;
            As[c4 * 4 + 2][l0] = av0.z;
            As[c4 * 4 + 3][l0] = av0.w;
            As[c4 * 4 + 0][l1] = av1.x;
            As[c4 * 4 + 1][l1] = av1.y;
            As[c4 * 4 + 2][l1] = av1.z;
            As[c4 * 4 + 3][l1] = av1.w;
        }
        // --- load W tile: 128 logical rows (gate-interleaved) x 16 cols ---
        {
            float4 wv0 = *(const float4*)(Wptr + (size_t)wrow0 * 1024 + kcol + c4 * 4);
            float4 wv1 = *(const float4*)(Wptr + (size_t)wrow1 * 1024 + kcol + c4 * 4);
            Ws[c4 * 4 + 0][l0] = wv0.x;
            Ws[c4 * 4 + 1][l0] = wv0.y;
            Ws[c4 * 4 + 2][l0] = wv0.z;
            Ws[c4 * 4 + 3][l0] = wv0.w;
            Ws[c4 * 4 + 0][l1] = wv1.x;
            Ws[c4 * 4 + 1][l1] = wv1.y;
            Ws[c4 * 4 + 2][l1] = wv1.z;
            Ws[c4 * 4 + 3][l1] = wv1.w;
        }
        __syncthreads();

        #pragma unroll
        for (int k = 0; k < BK; k++) {
            float af[8], wf[8];
            #pragma unroll
            for (int i = 0; i < 8; i++) af[i] = As[k][ty * 8 + i];
            #pragma unroll
            for (int j = 0; j < 8; j++) wf[j] = Ws[k][tx * 8 + j];
            #pragma unroll
            for (int i = 0; i < 8; i++)
                #pragma unroll
                for (int j = 0; j < 8; j++)
                    acc[i][j] = fmaf(af[i], wf[j], acc[i][j]);
        }
        __syncthreads();
    }

    // --- fused sLSTM epilogue ---
    // acc[i][cIdx]: logical col lc = tx*8 + cIdx = j*4 + gate
    //   => gate = cIdx & 3, j = tx*2 + (cIdx >> 2)
    const size_t BH = (size_t)BATCH * HDIM;
    #pragma unroll
    for (int i = 0; i < 8; i++) {
        const int row = bb * BM + ty * 8 + i;
        #pragma unroll
        for (int jj = 0; jj < 2; jj++) {
            const int jcol = bj * BN + tx * 2 + jj;
            float it = acc[i][jj * 4 + 0] + bias[0 * HDIM + jcol];
            float ft = acc[i][jj * 4 + 1] + bias[1 * HDIM + jcol];
            float zt = acc[i][jj * 4 + 2] + bias[2 * HDIM + jcol];
            float ot = acc[i][jj * 4 + 3] + bias[3 * HDIM + jcol];

            const size_t idx = (size_t)row * HDIM + jcol;
            const float mo = m[idx];
            const float mn = fmaxf(ft + mo, it);
            const float fg = __expf(ft + mo - mn);
            const float ig = __expf(it - mn);
            const float zg = tanhf(zt);
            const float og = 1.0f / (1.0f + __expf(-ot));
            const float cn = fg * c[idx] + ig * zg;
            const float nn = fg * n[idx] + ig;
            const float hn = og * (cn / fmaxf(fabsf(nn), 1.0f));

            out[idx]          = hn;
            out[BH + idx]     = cn;
            out[2 * BH + idx] = nn;
            out[3 * BH + idx] = mn;
        }
    }
}

extern "C" void kernel_launch(void* const* d_in, const int* in_sizes, int n_in,
                              void* d_out, int out_size) {
    const float* x    = (const float*)d_in[0];
    const float* h    = (const float*)d_in[1];
    const float* c    = (const float*)d_in[2];
    const float* n    = (const float*)d_in[3];
    const float* m    = (const float*)d_in[4];
    const float* Wx   = (const float*)d_in[5];
    const float* Wh   = (const float*)d_in[6];
    const float* bias = (const float*)d_in[7];
    float* out = (float*)d_out;

    dim3 grid(HDIM / BN, BATCH / BM);  // (32, 128)
    dim3 block(256);
    slstm_fused_kernel<<<grid, block>>>(x, h, c, n, m, Wx, Wh, bias, out);
}

// round 3
// speedup vs baseline: 3.6121x; 3.6121x over previous
#include <cuda_runtime.h>
#include <cuda_bf16.h>
#include <cstdint>
#include <math.h>

// ============================================================================
// sLSTM cell: gates = [x|h] @ [Wx|Wh]^T + b, exp-gate epilogue.
// bf16x3 split GEMM (hi*hi + hi*lo + lo*hi, fp32 accum) on the HMMA tensor
// pipe via legacy mma.sync.m16n8k16 (base PTX: works on plain sm_103 target).
// ============================================================================

#define BATCH 16384
#define HDIM  1024
#define NKT   64                    // 64 k-tiles of 32 over K=2048
#define PITCH 80                    // bytes per 32-bf16 smem row (64B + 16B pad)
#define PLANE_BYTES (128 * PITCH)   // 10240
#define STAGE_BYTES (4 * PLANE_BYTES)   // Ahi|Alo|Whi|Wlo = 40960
#define SMEM_TOTAL  (4 * STAGE_BYTES)   // 4 stages = 163840

// Scratch: per (row-tile, k-tile): [hi plane 4096 bf16][lo plane 4096 bf16]
__device__ __align__(16) __nv_bfloat16 g_Apack[(size_t)8192 * 8192]; // 134 MB
__device__ __align__(16) __nv_bfloat16 g_Wpack[(size_t)2048 * 8192]; //  33 MB

__device__ __forceinline__ uint32_t smem_u32(const void* p) {
    uint32_t a;
    asm("{ .reg .u64 t; cvta.to.shared.u64 t, %1; cvt.u32.u64 %0, t; }" : "=r"(a) : "l"(p));
    return a;
}
// pack {lo, hi} floats -> bf16x2 (lo in low half)
__device__ __forceinline__ uint32_t bf2(float lo, float hi) {
    uint32_t r;
    asm("cvt.rn.bf16x2.f32 %0, %1, %2;" : "=r"(r) : "f"(hi), "f"(lo));
    return r;
}

#define LDSM_X4(r, addr)                                                        \
    asm volatile("ldmatrix.sync.aligned.m8n8.x4.shared.b16 {%0,%1,%2,%3}, [%4];" \
                 : "=r"((r)[0]), "=r"((r)[1]), "=r"((r)[2]), "=r"((r)[3])       \
                 : "r"(addr))

#define MMA16816(d, a, b)                                                       \
    asm volatile("mma.sync.aligned.m16n8k16.row.col.f32.bf16.bf16.f32 "         \
                 "{%0,%1,%2,%3}, {%4,%5,%6,%7}, {%8,%9}, {%0,%1,%2,%3};"        \
                 : "+f"((d)[0]), "+f"((d)[1]), "+f"((d)[2]), "+f"((d)[3])       \
                 : "r"((a)[0]), "r"((a)[1]), "r"((a)[2]), "r"((a)[3]),          \
                   "r"((b)[0]), "r"((b)[1]))

#define CP_ASYNC16(dst, src) \
    asm volatile("cp.async.cg.shared.global [%0], [%1], 16;" :: "r"(dst), "l"(src))
#define CP_COMMIT() asm volatile("cp.async.commit_group;" ::: "memory")
#define CP_WAIT2()  asm volatile("cp.async.wait_group 2;" ::: "memory")

// ============================== pack kernel =================================
// One block per tile (128 rows x 32 k, fp32 -> bf16 hi/lo planes).
// A tiles: blocks [0, 8192): tile = mt*64 + kt, rows = batch rows.
// W tiles: blocks [8192, 10240): tile = nt*64 + kt, row r -> gate-blocked
//          weight row (r>>5)*HDIM + nt*32 + (r&31).
__global__ __launch_bounds__(128) void pack_kernel(
    const float* __restrict__ x, const float* __restrict__ h,
    const float* __restrict__ Wx, const float* __restrict__ Wh)
{
    const int bt = blockIdx.x, t = threadIdx.x;
    const bool isA = bt < 8192;
    const int tile = isA ? bt : bt - 8192;
    const int kt = tile & 63;
    const int rt = tile >> 6;
    const float* src = (kt < 32) ? (isA ? x : Wx) : (isA ? h : Wh);
    const int kbase = (kt & 31) * 32;
    __nv_bfloat16* dst = (isA ? g_Apack : g_Wpack) + (size_t)tile * 8192;

    #pragma unroll
    for (int i = 0; i < 8; i++) {
        const int cc = i * 128 + t;           // 1024 float4 chunks
        const int r = cc >> 3, k4 = cc & 7;
        const int grow = isA ? (rt * 128 + r)
                             : ((r >> 5) * HDIM + rt * 32 + (r & 31));
        float4 v = *(const float4*)(src + (size_t)grow * 1024 + kbase + k4 * 4);
        float hx = __bfloat162float(__float2bfloat16_rn(v.x));
        float hy = __bfloat162float(__float2bfloat16_rn(v.y));
        float hz = __bfloat162float(__float2bfloat16_rn(v.z));
        float hw = __bfloat162float(__float2bfloat16_rn(v.w));
        uint2 hi = make_uint2(bf2(hx, hy), bf2(hz, hw));
        uint2 lo = make_uint2(bf2(v.x - hx, v.y - hy), bf2(v.z - hz, v.w - hw));
        const int eoff = r * 32 + k4 * 4;     // bf16 elements
        *(uint2*)(dst + eoff)        = hi;    // hi plane
        *(uint2*)(dst + 4096 + eoff) = lo;    // lo plane
    }
}

// =============================== main kernel ================================
// 256 threads = 8 warps; warp (wm = wid>>2, wn = wid&3) computes 64x32.
__global__ __launch_bounds__(256, 1) void slstm_main(
    const float* __restrict__ c_in, const float* __restrict__ n_in,
    const float* __restrict__ m_in, const float* __restrict__ bias,
    float* __restrict__ out)
{
    extern __shared__ char smraw[];
    const uint32_t sb = smem_u32(smraw);
    const int t = threadIdx.x, lane = t & 31, wid = t >> 5;
    const int nt = blockIdx.x, mt = blockIdx.y;
    const int wm = wid >> 2, wn = wid & 3;

    const char* Abase = (const char*)g_Apack + (size_t)(mt * 64) * 16384;
    const char* Wbase = (const char*)g_Wpack + (size_t)(nt * 64) * 16384;

    // --- stage loader: 2048 x 16B chunks (A hi/lo, W hi/lo), 8 per thread ---
    auto load_stage = [&](int s, int kt) {
        const uint32_t d0 = sb + s * STAGE_BYTES;
        #pragma unroll
        for (int i = 0; i < 8; i++) {
            const int c = i * 256 + t;
            const int plane = c >> 9, w = c & 511;       // 512 chunks/plane
            const int row = w >> 2, ch = w & 3;
            const char* src = (plane < 2 ? Abase : Wbase)
                              + (size_t)kt * 16384 + (plane & 1) * 8192 + w * 16;
            const uint32_t dst = d0 + plane * PLANE_BYTES + row * PITCH + ch * 16;
            CP_ASYNC16(dst, src);
        }
    };

    // prologue: stages 0..2
    #pragma unroll
    for (int s = 0; s < 3; s++) { load_stage(s, s); CP_COMMIT(); }

    float acc[4][4][4];
    #pragma unroll
    for (int a = 0; a < 4; a++)
        #pragma unroll
        for (int b = 0; b < 4; b++)
            #pragma unroll
            for (int e = 0; e < 4; e++) acc[a][b][e] = 0.0f;

    for (int kt = 0; kt < NKT; kt++) {
        CP_WAIT2();
        __syncthreads();
        if (kt + 3 < NKT) load_stage((kt + 3) & 3, kt + 3);
        CP_COMMIT();

        const uint32_t st = sb + (kt & 3) * STAGE_BYTES;
        #pragma unroll
        for (int ks = 0; ks < 2; ks++) {       // two k16 steps per ktile
            uint32_t ahi[4][4], alo[4][4], whi[2][4], wlo[2][4];
            #pragma unroll
            for (int tm = 0; tm < 4; tm++) {
                const uint32_t r = wm * 64 + tm * 16 + ((lane >> 3) & 1) * 8 + (lane & 7);
                const uint32_t a = st + r * PITCH + ks * 32 + (lane >> 4) * 16;
                LDSM_X4(ahi[tm], a);
                LDSM_X4(alo[tm], a + PLANE_BYTES);
            }
            #pragma unroll
            for (int p = 0; p < 2; p++) {
                const uint32_t r = wn * 32 + p * 16 + ((lane >> 4) << 3) + (lane & 7);
                const uint32_t a = st + 2 * PLANE_BYTES + r * PITCH
                                 + ks * 32 + ((lane >> 3) & 1) * 16;
                LDSM_X4(whi[p], a);                 // W is n-row/k-contig: no .trans
                LDSM_X4(wlo[p], a + PLANE_BYTES);
            }
            #pragma unroll
            for (int tm = 0; tm < 4; tm++)
                #pragma unroll
                for (int tn = 0; tn < 4; tn++) {
                    const uint32_t* bh = &whi[tn >> 1][(tn & 1) * 2];
                    const uint32_t* bl = &wlo[tn >> 1][(tn & 1) * 2];
                    MMA16816(acc[tm][tn], ahi[tm], bh);
                    MMA16816(acc[tm][tn], ahi[tm], bl);
                    MMA16816(acc[tm][tn], alo[tm], bh);
                }
        }
    }

    // --- exchange accumulators through smem: [128][132] fp32 ---
    __syncthreads();
    float* smf = (float*)smraw;
    #pragma unroll
    for (int tm = 0; tm < 4; tm++)
        #pragma unroll
        for (int tn = 0; tn < 4; tn++) {
            const int row = wm * 64 + tm * 16 + (lane >> 2);
            const int col = wn * 32 + tn * 8 + (lane & 3) * 2;
            smf[row * 132 + col]           = acc[tm][tn][0];
            smf[row * 132 + col + 1]       = acc[tm][tn][1];
            smf[(row + 8) * 132 + col]     = acc[tm][tn][2];
            smf[(row + 8) * 132 + col + 1] = acc[tm][tn][3];
        }
    __syncthreads();

    // --- fused sLSTM epilogue: thread -> (16 rows, 1 hidden col) ---
    const int jj = t & 31;
    const int rb = (t >> 5) * 16;
    const int jcol = nt * 32 + jj;
    const float b_i = bias[jcol];
    const float b_f = bias[HDIM + jcol];
    const float b_z = bias[2 * HDIM + jcol];
    const float b_o = bias[3 * HDIM + jcol];
    const size_t BH = (size_t)BATCH * HDIM;

    #pragma unroll
    for (int rr = 0; rr < 16; rr++) {
        const int row = rb + rr;
        const size_t idx = (size_t)(mt * 128 + row) * HDIM + jcol;
        const float iv = smf[row * 132 + 0 * 32 + jj] + b_i;
        const float fv = smf[row * 132 + 1 * 32 + jj] + b_f;
        const float zv = smf[row * 132 + 2 * 32 + jj] + b_z;
        const float ov = smf[row * 132 + 3 * 32 + jj] + b_o;
        const float mo = m_in[idx];
        const float mn = fmaxf(fv + mo, iv);
        const float fg = __expf(fv + mo - mn);
        const float ig = __expf(iv - mn);
        const float zg = tanhf(zv);
        const float og = 1.0f / (1.0f + __expf(-ov));
        const float cn = fg * c_in[idx] + ig * zg;
        const float nn = fg * n_in[idx] + ig;
        const float hn = og * (cn / fmaxf(fabsf(nn), 1.0f));
        out[idx]          = hn;
        out[BH + idx]     = cn;
        out[2 * BH + idx] = nn;
        out[3 * BH + idx] = mn;
    }
}

// ================================ launch ====================================
extern "C" void kernel_launch(void* const* d_in, const int* in_sizes, int n_in,
                              void* d_out, int out_size) {
    const float* x    = (const float*)d_in[0];
    const float* h    = (const float*)d_in[1];
    const float* c    = (const float*)d_in[2];
    const float* n    = (const float*)d_in[3];
    const float* m    = (const float*)d_in[4];
    const float* Wx   = (const float*)d_in[5];
    const float* Wh   = (const float*)d_in[6];
    const float* bias = (const float*)d_in[7];
    float* out = (float*)d_out;

    pack_kernel<<<10240, 128>>>(x, h, Wx, Wh);

    static int configured = 0;
    cudaFuncSetAttribute(slstm_main, cudaFuncAttributeMaxDynamicSharedMemorySize,
                         SMEM_TOTAL);
    (void)configured;

    dim3 grid(32, 128);   // (nt, mt)
    slstm_main<<<grid, 256, SMEM_TOTAL>>>(c, n, m, bias, out);
}

// round 4
// speedup vs baseline: 4.8941x; 1.3549x over previous
#include <cuda_runtime.h>
#include <cuda_bf16.h>
#include <cstdint>
#include <math.h>

// ============================================================================
// sLSTM cell: gates = [x|h] @ [Wx|Wh]^T + b, exp-gate epilogue.
// bf16x3 split GEMM (hi*hi + hi*lo + lo*hi, fp32 accum) via mma.sync.m16n8k16.
// R4: 512 threads (16 warps, 4/SMSP), 64B-pitch XOR-swizzled smem, 5-stage
//     cp.async pipeline.
// ============================================================================

#define BATCH 16384
#define HDIM  1024
#define NKT   64                        // 64 k-tiles of 32 over K=2048
#define PLANE_BYTES 8192                // 128 rows x 64B, swizzled
#define STAGE_BYTES (4 * PLANE_BYTES)   // Ahi|Alo|Whi|Wlo = 32768
#define STAGES 5
#define SMEM_TOTAL (STAGES * STAGE_BYTES)   // 163840

// Scratch: per (row-tile, k-tile): [hi plane 4096 bf16][lo plane 4096 bf16]
__device__ __align__(16) __nv_bfloat16 g_Apack[(size_t)8192 * 8192]; // 134 MB
__device__ __align__(16) __nv_bfloat16 g_Wpack[(size_t)2048 * 8192]; //  33 MB

__device__ __forceinline__ uint32_t smem_u32(const void* p) {
    uint32_t a;
    asm("{ .reg .u64 t; cvta.to.shared.u64 t, %1; cvt.u32.u64 %0, t; }" : "=r"(a) : "l"(p));
    return a;
}
__device__ __forceinline__ uint32_t bf2(float lo, float hi) {
    uint32_t r;
    asm("cvt.rn.bf16x2.f32 %0, %1, %2;" : "=r"(r) : "f"(hi), "f"(lo));
    return r;
}

#define LDSM_X4(r, addr)                                                        \
    asm volatile("ldmatrix.sync.aligned.m8n8.x4.shared.b16 {%0,%1,%2,%3}, [%4];" \
                 : "=r"((r)[0]), "=r"((r)[1]), "=r"((r)[2]), "=r"((r)[3])       \
                 : "r"(addr))

#define MMA16816(d, a, b)                                                       \
    asm volatile("mma.sync.aligned.m16n8k16.row.col.f32.bf16.bf16.f32 "         \
                 "{%0,%1,%2,%3}, {%4,%5,%6,%7}, {%8,%9}, {%0,%1,%2,%3};"        \
                 : "+f"((d)[0]), "+f"((d)[1]), "+f"((d)[2]), "+f"((d)[3])       \
                 : "r"((a)[0]), "r"((a)[1]), "r"((a)[2]), "r"((a)[3]),          \
                   "r"((b)[0]), "r"((b)[1]))

#define CP_ASYNC16(dst, src) \
    asm volatile("cp.async.cg.shared.global [%0], [%1], 16;" :: "r"(dst), "l"(src))
#define CP_COMMIT() asm volatile("cp.async.commit_group;" ::: "memory")
#define CP_WAIT3()  asm volatile("cp.async.wait_group 3;" ::: "memory")

// swizzled byte offset within an 8KB plane for (row, 16B-chunk)
__device__ __forceinline__ uint32_t swz(int row, int ch) {
    return (uint32_t)(row * 64 + ((ch ^ ((row >> 1) & 3)) << 4));
}

// ============================== pack kernel =================================
__global__ __launch_bounds__(128) void pack_kernel(
    const float* __restrict__ x, const float* __restrict__ h,
    const float* __restrict__ Wx, const float* __restrict__ Wh)
{
    const int bt = blockIdx.x, t = threadIdx.x;
    const bool isA = bt < 8192;
    const int tile = isA ? bt : bt - 8192;
    const int kt = tile & 63;
    const int rt = tile >> 6;
    const float* src = (kt < 32) ? (isA ? x : Wx) : (isA ? h : Wh);
    const int kbase = (kt & 31) * 32;
    __nv_bfloat16* dst = (isA ? g_Apack : g_Wpack) + (size_t)tile * 8192;

    #pragma unroll
    for (int i = 0; i < 8; i++) {
        const int cc = i * 128 + t;           // 1024 float4 chunks
        const int r = cc >> 3, k4 = cc & 7;
        const int grow = isA ? (rt * 128 + r)
                             : ((r >> 5) * HDIM + rt * 32 + (r & 31));
        float4 v = *(const float4*)(src + (size_t)grow * 1024 + kbase + k4 * 4);
        float hx = __bfloat162float(__float2bfloat16_rn(v.x));
        float hy = __bfloat162float(__float2bfloat16_rn(v.y));
        float hz = __bfloat162float(__float2bfloat16_rn(v.z));
        float hw = __bfloat162float(__float2bfloat16_rn(v.w));
        uint2 hi = make_uint2(bf2(hx, hy), bf2(hz, hw));
        uint2 lo = make_uint2(bf2(v.x - hx, v.y - hy), bf2(v.z - hz, v.w - hw));
        const int eoff = r * 32 + k4 * 4;
        *(uint2*)(dst + eoff)        = hi;
        *(uint2*)(dst + 4096 + eoff) = lo;
    }
}

// =============================== main kernel ================================
// 512 threads = 16 warps in 4x4 grid; warp (wm, wn) computes 32x32.
__global__ __launch_bounds__(512, 1) void slstm_main(
    const float* __restrict__ c_in, const float* __restrict__ n_in,
    const float* __restrict__ m_in, const float* __restrict__ bias,
    float* __restrict__ out)
{
    extern __shared__ char smraw[];
    const uint32_t sb = smem_u32(smraw);
    const int t = threadIdx.x, lane = t & 31, wid = t >> 5;
    const int nt = blockIdx.x, mt = blockIdx.y;
    const int wm = wid >> 2, wn = wid & 3;

    const char* Abase = (const char*)g_Apack + (size_t)(mt * 64) * 16384;
    const char* Wbase = (const char*)g_Wpack + (size_t)(nt * 64) * 16384;

    // --- stage loader: 2048 x 16B chunks, 4 per thread, swizzled dst ---
    auto load_stage = [&](int s, int kt) {
        const uint32_t d0 = sb + s * STAGE_BYTES;
        #pragma unroll
        for (int i = 0; i < 4; i++) {
            const int c = i * 512 + t;
            const int plane = c >> 9, w = c & 511;
            const int row = w >> 2, ch = w & 3;
            const char* src = (plane < 2 ? Abase : Wbase)
                              + (size_t)kt * 16384 + (plane & 1) * 8192 + w * 16;
            const uint32_t dst = d0 + plane * PLANE_BYTES + swz(row, ch);
            CP_ASYNC16(dst, src);
        }
    };

    // prologue: stages 0..3
    #pragma unroll
    for (int s = 0; s < 4; s++) { load_stage(s, s); CP_COMMIT(); }

    float acc[2][4][4];
    #pragma unroll
    for (int a = 0; a < 2; a++)
        #pragma unroll
        for (int b = 0; b < 4; b++)
            #pragma unroll
            for (int e = 0; e < 4; e++) acc[a][b][e] = 0.0f;

    int cs = 0, ls = 4;                      // compute slot / load slot
    for (int kt = 0; kt < NKT; kt++) {
        CP_WAIT3();
        __syncthreads();
        if (kt + 4 < NKT) load_stage(ls, kt + 4);
        CP_COMMIT();
        if (++ls == STAGES) ls = 0;

        const uint32_t st = sb + cs * STAGE_BYTES;
        if (++cs == STAGES) cs = 0;

        #pragma unroll
        for (int ks = 0; ks < 2; ks++) {
            uint32_t ahi[2][4], alo[2][4], whi[2][4], wlo[2][4];
            #pragma unroll
            for (int tm = 0; tm < 2; tm++) {
                const int r = wm * 32 + tm * 16 + (lane & 15);
                const int ch = ks * 2 + (lane >> 4);
                const uint32_t a = st + swz(r, ch);
                LDSM_X4(ahi[tm], a);
                LDSM_X4(alo[tm], a + PLANE_BYTES);
            }
            #pragma unroll
            for (int p = 0; p < 2; p++) {
                // address permutation puts both k-halves of one n8 group in
                // consecutive regs: r0=(n0-7,k0-7), r1=(n0-7,k8-15), ...
                const int r = wn * 32 + p * 16 + ((lane >> 4) << 3) + (lane & 7);
                const int ch = ks * 2 + ((lane >> 3) & 1);
                const uint32_t a = st + 2 * PLANE_BYTES + swz(r, ch);
                LDSM_X4(whi[p], a);
                LDSM_X4(wlo[p], a + PLANE_BYTES);
            }
            #pragma unroll
            for (int tm = 0; tm < 2; tm++)
                #pragma unroll
                for (int tn = 0; tn < 4; tn++) {
                    const uint32_t* bh = &whi[tn >> 1][(tn & 1) * 2];
                    const uint32_t* bl = &wlo[tn >> 1][(tn & 1) * 2];
                    MMA16816(acc[tm][tn], ahi[tm], bh);
                    MMA16816(acc[tm][tn], ahi[tm], bl);
                    MMA16816(acc[tm][tn], alo[tm], bh);
                }
        }
    }

    // --- exchange accumulators through smem: [128][132] fp32 ---
    __syncthreads();
    float* smf = (float*)smraw;
    #pragma unroll
    for (int tm = 0; tm < 2; tm++)
        #pragma unroll
        for (int tn = 0; tn < 4; tn++) {
            const int row = wm * 32 + tm * 16 + (lane >> 2);
            const int col = wn * 32 + tn * 8 + (lane & 3) * 2;
            smf[row * 132 + col]           = acc[tm][tn][0];
            smf[row * 132 + col + 1]       = acc[tm][tn][1];
            smf[(row + 8) * 132 + col]     = acc[tm][tn][2];
            smf[(row + 8) * 132 + col + 1] = acc[tm][tn][3];
        }
    __syncthreads();

    // --- fused sLSTM epilogue: thread -> (8 rows, 1 hidden col) ---
    const int jj = t & 31;
    const int rb = (t >> 5) * 8;
    const int jcol = nt * 32 + jj;
    const float b_i = bias[jcol];
    const float b_f = bias[HDIM + jcol];
    const float b_z = bias[2 * HDIM + jcol];
    const float b_o = bias[3 * HDIM + jcol];
    const size_t BH = (size_t)BATCH * HDIM;

    #pragma unroll
    for (int rr = 0; rr < 8; rr++) {
        const int row = rb + rr;
        const size_t idx = (size_t)(mt * 128 + row) * HDIM + jcol;
        const float iv = smf[row * 132 + 0 * 32 + jj] + b_i;
        const float fv = smf[row * 132 + 1 * 32 + jj] + b_f;
        const float zv = smf[row * 132 + 2 * 32 + jj] + b_z;
        const float ov = smf[row * 132 + 3 * 32 + jj] + b_o;
        const float mo = m_in[idx];
        const float mn = fmaxf(fv + mo, iv);
        const float fg = __expf(fv + mo - mn);
        const float ig = __expf(iv - mn);
        const float zg = tanhf(zv);
        const float og = 1.0f / (1.0f + __expf(-ov));
        const float cn = fg * c_in[idx] + ig * zg;
        const float nn = fg * n_in[idx] + ig;
        const float hn = og * (cn / fmaxf(fabsf(nn), 1.0f));
        out[idx]          = hn;
        out[BH + idx]     = cn;
        out[2 * BH + idx] = nn;
        out[3 * BH + idx] = mn;
    }
}

// ================================ launch ====================================
extern "C" void kernel_launch(void* const* d_in, const int* in_sizes, int n_in,
                              void* d_out, int out_size) {
    const float* x    = (const float*)d_in[0];
    const float* h    = (const float*)d_in[1];
    const float* c    = (const float*)d_in[2];
    const float* n    = (const float*)d_in[3];
    const float* m    = (const float*)d_in[4];
    const float* Wx   = (const float*)d_in[5];
    const float* Wh   = (const float*)d_in[6];
    const float* bias = (const float*)d_in[7];
    float* out = (float*)d_out;

    pack_kernel<<<10240, 128>>>(x, h, Wx, Wh);

    cudaFuncSetAttribute(slstm_main, cudaFuncAttributeMaxDynamicSharedMemorySize,
                         SMEM_TOTAL);
    dim3 grid(32, 128);   // (nt, mt)
    slstm_main<<<grid, 512, SMEM_TOTAL>>>(c, n, m, bias, out);
}

// round 5
// speedup vs baseline: 6.4267x; 1.3132x over previous
#include <cuda_runtime.h>
#include <cuda_fp16.h>
#include <cstdint>
#include <math.h>

// ============================================================================
// sLSTM cell: gates = [x|h] @ [Wx|Wh]^T + b, exp-gate epilogue.
// fp16 2-term split GEMM: gates = x16 @ (Wh_hi + Wh_lo)^T, fp32 accumulate.
//   activations: single fp16 plane (rounding error 2^-11 -> rel_err ~2.5e-4)
//   weights:     fp16 hi + fp16 lo (exact to 2^-22)
// mma.sync.m16n8k16 (legacy HMMA pipe, rt~8cyc/SMSP), 512 threads, 8-stage
// cp.async pipeline, XOR-swizzled 64B-pitch smem.
// ============================================================================

#define BATCH 16384
#define HDIM  1024
#define NKT   64                         // 64 k-tiles of 32 over K=2048
#define APLANE 8192                      // 128 rows x 32 k x fp16
#define STAGE_BYTES (3 * APLANE)         // A | Whi | Wlo = 24576
#define STAGES 8
#define SMEM_TOTAL (STAGES * STAGE_BYTES)    // 196608

// Scratch: A single plane per tile (4096 half), W hi+lo per tile (8192 half)
__device__ __align__(16) __half g_Apack[(size_t)8192 * 4096]; // 67 MB
__device__ __align__(16) __half g_Wpack[(size_t)2048 * 8192]; // 33 MB

__device__ __forceinline__ uint32_t smem_u32(const void* p) {
    uint32_t a;
    asm("{ .reg .u64 t; cvta.to.shared.u64 t, %1; cvt.u32.u64 %0, t; }" : "=r"(a) : "l"(p));
    return a;
}

#define LDSM_X4(r, addr)                                                        \
    asm volatile("ldmatrix.sync.aligned.m8n8.x4.shared.b16 {%0,%1,%2,%3}, [%4];" \
                 : "=r"((r)[0]), "=r"((r)[1]), "=r"((r)[2]), "=r"((r)[3])       \
                 : "r"(addr))

#define MMA16816(d, a, b)                                                       \
    asm volatile("mma.sync.aligned.m16n8k16.row.col.f32.f16.f16.f32 "           \
                 "{%0,%1,%2,%3}, {%4,%5,%6,%7}, {%8,%9}, {%0,%1,%2,%3};"        \
                 : "+f"((d)[0]), "+f"((d)[1]), "+f"((d)[2]), "+f"((d)[3])       \
                 : "r"((a)[0]), "r"((a)[1]), "r"((a)[2]), "r"((a)[3]),          \
                   "r"((b)[0]), "r"((b)[1]))

#define CP_ASYNC16(dst, src) \
    asm volatile("cp.async.cg.shared.global [%0], [%1], 16;" :: "r"(dst), "l"(src))
#define CP_COMMIT() asm volatile("cp.async.commit_group;" ::: "memory")
#define CP_WAIT6()  asm volatile("cp.async.wait_group 6;" ::: "memory")

// swizzled byte offset within an 8KB plane for (row, 16B-chunk)
__device__ __forceinline__ uint32_t swz(int row, int ch) {
    return (uint32_t)(row * 64 + ((ch ^ ((row >> 1) & 3)) << 4));
}

// ============================== pack kernel =================================
// A tiles (blocks [0,8192)): 128 batch rows x 32 k -> single fp16 plane.
// W tiles (blocks [8192,10240)): gate-blocked rows -> fp16 hi + lo planes.
__global__ __launch_bounds__(128) void pack_kernel(
    const float* __restrict__ x, const float* __restrict__ h,
    const float* __restrict__ Wx, const float* __restrict__ Wh)
{
    const int bt = blockIdx.x, t = threadIdx.x;
    const bool isA = bt < 8192;
    const int tile = isA ? bt : bt - 8192;
    const int kt = tile & 63;
    const int rt = tile >> 6;
    const float* src = (kt < 32) ? (isA ? x : Wx) : (isA ? h : Wh);
    const int kbase = (kt & 31) * 32;

    if (isA) {
        __half* dst = g_Apack + (size_t)tile * 4096;
        #pragma unroll
        for (int i = 0; i < 8; i++) {
            const int cc = i * 128 + t;
            const int r = cc >> 3, k4 = cc & 7;
            float4 v = *(const float4*)(src + (size_t)(rt * 128 + r) * 1024 + kbase + k4 * 4);
            __half2 p0 = __floats2half2_rn(v.x, v.y);
            __half2 p1 = __floats2half2_rn(v.z, v.w);
            *(uint2*)(dst + r * 32 + k4 * 4) =
                make_uint2(*(uint32_t*)&p0, *(uint32_t*)&p1);
        }
    } else {
        __half* dst = g_Wpack + (size_t)tile * 8192;
        #pragma unroll
        for (int i = 0; i < 8; i++) {
            const int cc = i * 128 + t;
            const int r = cc >> 3, k4 = cc & 7;
            const int grow = (r >> 5) * HDIM + rt * 32 + (r & 31);
            float4 v = *(const float4*)(src + (size_t)grow * 1024 + kbase + k4 * 4);
            float hx = __half2float(__float2half_rn(v.x));
            float hy = __half2float(__float2half_rn(v.y));
            float hz = __half2float(__float2half_rn(v.z));
            float hw = __half2float(__float2half_rn(v.w));
            __half2 h0 = __floats2half2_rn(hx, hy);
            __half2 h1 = __floats2half2_rn(hz, hw);
            __half2 l0 = __floats2half2_rn(v.x - hx, v.y - hy);
            __half2 l1 = __floats2half2_rn(v.z - hz, v.w - hw);
            const int eoff = r * 32 + k4 * 4;
            *(uint2*)(dst + eoff)        = make_uint2(*(uint32_t*)&h0, *(uint32_t*)&h1);
            *(uint2*)(dst + 4096 + eoff) = make_uint2(*(uint32_t*)&l0, *(uint32_t*)&l1);
        }
    }
}

// =============================== main kernel ================================
// 512 threads = 16 warps in 4x4 grid; warp (wm, wn) computes 32x32.
__global__ __launch_bounds__(512, 1) void slstm_main(
    const float* __restrict__ c_in, const float* __restrict__ n_in,
    const float* __restrict__ m_in, const float* __restrict__ bias,
    float* __restrict__ out)
{
    extern __shared__ char smraw[];
    const uint32_t sb = smem_u32(smraw);
    const int t = threadIdx.x, lane = t & 31, wid = t >> 5;
    const int nt = blockIdx.x, mt = blockIdx.y;
    const int wm = wid >> 2, wn = wid & 3;

    const char* Abase = (const char*)g_Apack + (size_t)(mt * 64) * 8192;
    const char* Wbase = (const char*)g_Wpack + (size_t)(nt * 64) * 16384;

    // --- stage loader: 1536 x 16B chunks (A | Whi | Wlo), 3 per thread ---
    auto load_stage = [&](int s, int kt) {
        const uint32_t d0 = sb + s * STAGE_BYTES;
        #pragma unroll
        for (int i = 0; i < 3; i++) {
            const int w = t;                          // 512 chunks per plane
            const int row = w >> 2, ch = w & 3;
            const char* src;
            if (i == 0)      src = Abase + (size_t)kt * 8192 + w * 16;
            else if (i == 1) src = Wbase + (size_t)kt * 16384 + w * 16;
            else             src = Wbase + (size_t)kt * 16384 + 8192 + w * 16;
            CP_ASYNC16(d0 + i * APLANE + swz(row, ch), src);
        }
    };

    // prologue: stages 0..6
    #pragma unroll
    for (int s = 0; s < 7; s++) { load_stage(s, s); CP_COMMIT(); }

    float acc[2][4][4];
    #pragma unroll
    for (int a = 0; a < 2; a++)
        #pragma unroll
        for (int b = 0; b < 4; b++)
            #pragma unroll
            for (int e = 0; e < 4; e++) acc[a][b][e] = 0.0f;

    int cs = 0, ls = 7;
    for (int kt = 0; kt < NKT; kt++) {
        CP_WAIT6();
        __syncthreads();
        if (kt + 7 < NKT) load_stage(ls, kt + 7);
        CP_COMMIT();
        if (++ls == STAGES) ls = 0;

        const uint32_t st = sb + cs * STAGE_BYTES;
        if (++cs == STAGES) cs = 0;

        #pragma unroll
        for (int ks = 0; ks < 2; ks++) {
            uint32_t afr[2][4], whi[2][4], wlo[2][4];
            #pragma unroll
            for (int tm = 0; tm < 2; tm++) {
                const int r = wm * 32 + tm * 16 + (lane & 15);
                const int ch = ks * 2 + (lane >> 4);
                LDSM_X4(afr[tm], st + swz(r, ch));
            }
            #pragma unroll
            for (int p = 0; p < 2; p++) {
                const int r = wn * 32 + p * 16 + ((lane >> 4) << 3) + (lane & 7);
                const int ch = ks * 2 + ((lane >> 3) & 1);
                const uint32_t a = st + APLANE + swz(r, ch);
                LDSM_X4(whi[p], a);
                LDSM_X4(wlo[p], a + APLANE);
            }
            #pragma unroll
            for (int tm = 0; tm < 2; tm++)
                #pragma unroll
                for (int tn = 0; tn < 4; tn++) {
                    MMA16816(acc[tm][tn], afr[tm], (&whi[tn >> 1][(tn & 1) * 2]));
                    MMA16816(acc[tm][tn], afr[tm], (&wlo[tn >> 1][(tn & 1) * 2]));
                }
        }
    }

    // --- exchange accumulators through smem: [128][132] fp32 ---
    __syncthreads();
    float* smf = (float*)smraw;
    #pragma unroll
    for (int tm = 0; tm < 2; tm++)
        #pragma unroll
        for (int tn = 0; tn < 4; tn++) {
            const int row = wm * 32 + tm * 16 + (lane >> 2);
            const int col = wn * 32 + tn * 8 + (lane & 3) * 2;
            smf[row * 132 + col]           = acc[tm][tn][0];
            smf[row * 132 + col + 1]       = acc[tm][tn][1];
            smf[(row + 8) * 132 + col]     = acc[tm][tn][2];
            smf[(row + 8) * 132 + col + 1] = acc[tm][tn][3];
        }
    __syncthreads();

    // --- fused sLSTM epilogue: thread -> (8 rows, 1 hidden col) ---
    const int jj = t & 31;
    const int rb = (t >> 5) * 8;
    const int jcol = nt * 32 + jj;
    const float b_i = bias[jcol];
    const float b_f = bias[HDIM + jcol];
    const float b_z = bias[2 * HDIM + jcol];
    const float b_o = bias[3 * HDIM + jcol];
    const size_t BH = (size_t)BATCH * HDIM;

    #pragma unroll
    for (int rr = 0; rr < 8; rr++) {
        const int row = rb + rr;
        const size_t idx = (size_t)(mt * 128 + row) * HDIM + jcol;
        const float iv = smf[row * 132 + 0 * 32 + jj] + b_i;
        const float fv = smf[row * 132 + 1 * 32 + jj] + b_f;
        const float zv = smf[row * 132 + 2 * 32 + jj] + b_z;
        const float ov = smf[row * 132 + 3 * 32 + jj] + b_o;
        const float mo = m_in[idx];
        const float mn = fmaxf(fv + mo, iv);
        const float fg = __expf(fv + mo - mn);
        const float ig = __expf(iv - mn);
        const float zg = tanhf(zv);
        const float og = 1.0f / (1.0f + __expf(-ov));
        const float cn = fg * c_in[idx] + ig * zg;
        const float nn = fg * n_in[idx] + ig;
        const float hn = og * (cn / fmaxf(fabsf(nn), 1.0f));
        out[idx]          = hn;
        out[BH + idx]     = cn;
        out[2 * BH + idx] = nn;
        out[3 * BH + idx] = mn;
    }
}

// ================================ launch ====================================
extern "C" void kernel_launch(void* const* d_in, const int* in_sizes, int n_in,
                              void* d_out, int out_size) {
    const float* x    = (const float*)d_in[0];
    const float* h    = (const float*)d_in[1];
    const float* c    = (const float*)d_in[2];
    const float* n    = (const float*)d_in[3];
    const float* m    = (const float*)d_in[4];
    const float* Wx   = (const float*)d_in[5];
    const float* Wh   = (const float*)d_in[6];
    const float* bias = (const float*)d_in[7];
    float* out = (float*)d_out;

    pack_kernel<<<10240, 128>>>(x, h, Wx, Wh);

    cudaFuncSetAttribute(slstm_main, cudaFuncAttributeMaxDynamicSharedMemorySize,
                         SMEM_TOTAL);
    dim3 grid(32, 128);   // (nt, mt)
    slstm_main<<<grid, 512, SMEM_TOTAL>>>(c, n, m, bias, out);
}

// round 6
// speedup vs baseline: 7.0330x; 1.0943x over previous
#include <cuda_runtime.h>
#include <cuda_fp16.h>
#include <cstdint>
#include <math.h>

// ============================================================================
// sLSTM cell: gates = [x|h] @ [Wx|Wh]^T + b, exp-gate epilogue.
// fp16 2-term split GEMM (x16 @ (Whi + Wlo)^T, fp32 accum), mma.sync.m16n8k16.
// R6: CTA tile 128x256 (4 gates x 64 hidden), warp tile 32x64 -> LDSM bytes
//     per MMA drop 192B -> 80B (smem crossbar was co-saturated with tensor).
// ============================================================================

#define BATCH 16384
#define HDIM  1024
#define NKT   64                         // 64 k-tiles of 32 over K=2048
#define APLANE 8192                      // one 128-row x 32-k fp16 plane
#define STAGE_BYTES (5 * APLANE)         // A | Whi_q0 | Whi_q1 | Wlo_q0 | Wlo_q1
#define STAGES 4
#define SMEM_TOTAL (STAGES * STAGE_BYTES)    // 163840

// Scratch (same layout as R5): A single fp16 plane per (mt,kt) tile;
// W hi+lo planes per (rt,kt) tile, rt over 32-hidden blocks, gate-blocked rows.
__device__ __align__(16) __half g_Apack[(size_t)8192 * 4096]; // 67 MB
__device__ __align__(16) __half g_Wpack[(size_t)2048 * 8192]; // 33 MB

__device__ __forceinline__ uint32_t smem_u32(const void* p) {
    uint32_t a;
    asm("{ .reg .u64 t; cvta.to.shared.u64 t, %1; cvt.u32.u64 %0, t; }" : "=r"(a) : "l"(p));
    return a;
}

#define LDSM_X4(r, addr)                                                        \
    asm volatile("ldmatrix.sync.aligned.m8n8.x4.shared.b16 {%0,%1,%2,%3}, [%4];" \
                 : "=r"((r)[0]), "=r"((r)[1]), "=r"((r)[2]), "=r"((r)[3])       \
                 : "r"(addr))

#define MMA16816(d, a, b)                                                       \
    asm volatile("mma.sync.aligned.m16n8k16.row.col.f32.f16.f16.f32 "           \
                 "{%0,%1,%2,%3}, {%4,%5,%6,%7}, {%8,%9}, {%0,%1,%2,%3};"        \
                 : "+f"((d)[0]), "+f"((d)[1]), "+f"((d)[2]), "+f"((d)[3])       \
                 : "r"((a)[0]), "r"((a)[1]), "r"((a)[2]), "r"((a)[3]),          \
                   "r"((b)[0]), "r"((b)[1]))

#define CP_ASYNC16(dst, src) \
    asm volatile("cp.async.cg.shared.global [%0], [%1], 16;" :: "r"(dst), "l"(src))
#define CP_COMMIT() asm volatile("cp.async.commit_group;" ::: "memory")
#define CP_WAIT2()  asm volatile("cp.async.wait_group 2;" ::: "memory")

// swizzled byte offset within an 8KB plane for (row, 16B-chunk)
__device__ __forceinline__ uint32_t swz(int row, int ch) {
    return (uint32_t)(row * 64 + ((ch ^ ((row >> 1) & 3)) << 4));
}

// ============================== pack kernel (unchanged) =====================
__global__ __launch_bounds__(128) void pack_kernel(
    const float* __restrict__ x, const float* __restrict__ h,
    const float* __restrict__ Wx, const float* __restrict__ Wh)
{
    const int bt = blockIdx.x, t = threadIdx.x;
    const bool isA = bt < 8192;
    const int tile = isA ? bt : bt - 8192;
    const int kt = tile & 63;
    const int rt = tile >> 6;
    const float* src = (kt < 32) ? (isA ? x : Wx) : (isA ? h : Wh);
    const int kbase = (kt & 31) * 32;

    if (isA) {
        __half* dst = g_Apack + (size_t)tile * 4096;
        #pragma unroll
        for (int i = 0; i < 8; i++) {
            const int cc = i * 128 + t;
            const int r = cc >> 3, k4 = cc & 7;
            float4 v = *(const float4*)(src + (size_t)(rt * 128 + r) * 1024 + kbase + k4 * 4);
            __half2 p0 = __floats2half2_rn(v.x, v.y);
            __half2 p1 = __floats2half2_rn(v.z, v.w);
            *(uint2*)(dst + r * 32 + k4 * 4) =
                make_uint2(*(uint32_t*)&p0, *(uint32_t*)&p1);
        }
    } else {
        __half* dst = g_Wpack + (size_t)tile * 8192;
        #pragma unroll
        for (int i = 0; i < 8; i++) {
            const int cc = i * 128 + t;
            const int r = cc >> 3, k4 = cc & 7;
            const int grow = (r >> 5) * HDIM + rt * 32 + (r & 31);
            float4 v = *(const float4*)(src + (size_t)grow * 1024 + kbase + k4 * 4);
            float hx = __half2float(__float2half_rn(v.x));
            float hy = __half2float(__float2half_rn(v.y));
            float hz = __half2float(__float2half_rn(v.z));
            float hw = __half2float(__float2half_rn(v.w));
            __half2 h0 = __floats2half2_rn(hx, hy);
            __half2 h1 = __floats2half2_rn(hz, hw);
            __half2 l0 = __floats2half2_rn(v.x - hx, v.y - hy);
            __half2 l1 = __floats2half2_rn(v.z - hz, v.w - hw);
            const int eoff = r * 32 + k4 * 4;
            *(uint2*)(dst + eoff)        = make_uint2(*(uint32_t*)&h0, *(uint32_t*)&h1);
            *(uint2*)(dst + 4096 + eoff) = make_uint2(*(uint32_t*)&l0, *(uint32_t*)&l1);
        }
    }
}

// =============================== main kernel ================================
// 512 threads = 16 warps in 4x4 grid; warp (wm, wn) computes 32 rows x 64 cols.
// N=256 split as two 128-col halves (hidden sub-blocks q=0,1), each half in the
// R5 gate-blocked layout (col within half = gate*32 + jj).
__global__ __launch_bounds__(512, 1) void slstm_main(
    const float* __restrict__ c_in, const float* __restrict__ n_in,
    const float* __restrict__ m_in, const float* __restrict__ bias,
    float* __restrict__ out)
{
    extern __shared__ char smraw[];
    const uint32_t sb = smem_u32(smraw);
    const int t = threadIdx.x, lane = t & 31, wid = t >> 5;
    const int nt = blockIdx.x, mt = blockIdx.y;
    const int wm = wid >> 2, wn = wid & 3;

    const char* Abase  = (const char*)g_Apack + (size_t)(mt * 64) * 8192;
    const char* Wbase0 = (const char*)g_Wpack + (size_t)((2 * nt + 0) * 64) * 16384;
    const char* Wbase1 = (const char*)g_Wpack + (size_t)((2 * nt + 1) * 64) * 16384;

    // --- stage loader: 5 planes x 512 chunks, 5 x 16B per thread ---
    const int lrow = t >> 2, lch = t & 3;
    const uint32_t ldoff = swz(lrow, lch);
    auto load_stage = [&](int s, int kt) {
        const uint32_t d0 = sb + s * STAGE_BYTES + ldoff;
        const size_t wo = (size_t)kt * 16384 + t * 16;
        CP_ASYNC16(d0,              Abase + (size_t)kt * 8192 + t * 16);
        CP_ASYNC16(d0 + 1 * APLANE, Wbase0 + wo);
        CP_ASYNC16(d0 + 2 * APLANE, Wbase1 + wo);
        CP_ASYNC16(d0 + 3 * APLANE, Wbase0 + wo + 8192);
        CP_ASYNC16(d0 + 4 * APLANE, Wbase1 + wo + 8192);
    };

    // prologue: stages 0..2
    #pragma unroll
    for (int s = 0; s < 3; s++) { load_stage(s, s); CP_COMMIT(); }

    float acc[2][8][4];
    #pragma unroll
    for (int a = 0; a < 2; a++)
        #pragma unroll
        for (int b = 0; b < 8; b++)
            #pragma unroll
            for (int e = 0; e < 4; e++) acc[a][b][e] = 0.0f;

    const int q = wn >> 1;                 // W sub-plane
    const int rbase = (wn & 1) * 64;       // row base within sub-plane
    int cs = 0, ls = 3;
    for (int kt = 0; kt < NKT; kt++) {
        CP_WAIT2();
        __syncthreads();
        if (kt + 3 < NKT) load_stage(ls, kt + 3);
        CP_COMMIT();
        if (++ls == STAGES) ls = 0;

        const uint32_t st = sb + cs * STAGE_BYTES;
        if (++cs == STAGES) cs = 0;
        const uint32_t whibase = st + APLANE * (1 + q);

        #pragma unroll
        for (int ks = 0; ks < 2; ks++) {
            uint32_t afr[2][4];
            #pragma unroll
            for (int tm = 0; tm < 2; tm++) {
                const int r = wm * 32 + tm * 16 + (lane & 15);
                const int ch = ks * 2 + (lane >> 4);
                LDSM_X4(afr[tm], st + swz(r, ch));
            }
            #pragma unroll
            for (int ph = 0; ph < 2; ph++) {       // p = ph*2 + pp
                uint32_t whi[2][4], wlo[2][4];
                #pragma unroll
                for (int pp = 0; pp < 2; pp++) {
                    const int p = ph * 2 + pp;
                    const int r = rbase + p * 16 + ((lane >> 4) << 3) + (lane & 7);
                    const int ch = ks * 2 + ((lane >> 3) & 1);
                    const uint32_t a = whibase + swz(r, ch);
                    LDSM_X4(whi[pp], a);
                    LDSM_X4(wlo[pp], a + 2 * APLANE);
                }
                #pragma unroll
                for (int tm = 0; tm < 2; tm++)
                    #pragma unroll
                    for (int pp = 0; pp < 2; pp++)
                        #pragma unroll
                        for (int hf = 0; hf < 2; hf++) {
                            const int tn = ph * 4 + pp * 2 + hf;
                            MMA16816(acc[tm][tn], afr[tm], (&whi[pp][hf * 2]));
                            MMA16816(acc[tm][tn], afr[tm], (&wlo[pp][hf * 2]));
                        }
            }
        }
    }

    // --- exchange accumulators through smem: [128][260] fp32 ---
    __syncthreads();
    float* smf = (float*)smraw;
    #pragma unroll
    for (int tm = 0; tm < 2; tm++)
        #pragma unroll
        for (int tn = 0; tn < 8; tn++) {
            const int row = wm * 32 + tm * 16 + (lane >> 2);
            const int col = wn * 64 + tn * 8 + (lane & 3) * 2;
            smf[row * 260 + col]           = acc[tm][tn][0];
            smf[row * 260 + col + 1]       = acc[tm][tn][1];
            smf[(row + 8) * 260 + col]     = acc[tm][tn][2];
            smf[(row + 8) * 260 + col + 1] = acc[tm][tn][3];
        }
    __syncthreads();

    // --- fused sLSTM epilogue: thread -> (16 rows, 1 hidden col) ---
    // smf column for (gate g, hidden jh): (jh>>5)*128 + g*32 + (jh&31)
    const int jh = t & 63;
    const int rb = (t >> 6) * 16;
    const int cb = (jh >> 5) * 128 + (jh & 31);
    const int jcol = nt * 64 + jh;
    const float b_i = bias[jcol];
    const float b_f = bias[HDIM + jcol];
    const float b_z = bias[2 * HDIM + jcol];
    const float b_o = bias[3 * HDIM + jcol];
    const size_t BH = (size_t)BATCH * HDIM;

    #pragma unroll
    for (int rr = 0; rr < 16; rr++) {
        const int row = rb + rr;
        const size_t idx = (size_t)(mt * 128 + row) * HDIM + jcol;
        const float iv = smf[row * 260 + cb + 0 * 32] + b_i;
        const float fv = smf[row * 260 + cb + 1 * 32] + b_f;
        const float zv = smf[row * 260 + cb + 2 * 32] + b_z;
        const float ov = smf[row * 260 + cb + 3 * 32] + b_o;
        const float mo = m_in[idx];
        const float mn = fmaxf(fv + mo, iv);
        const float fg = __expf(fv + mo - mn);
        const float ig = __expf(iv - mn);
        const float zg = tanhf(zv);
        const float og = 1.0f / (1.0f + __expf(-ov));
        const float cn = fg * c_in[idx] + ig * zg;
        const float nn = fg * n_in[idx] + ig;
        const float hn = og * (cn / fmaxf(fabsf(nn), 1.0f));
        out[idx]          = hn;
        out[BH + idx]     = cn;
        out[2 * BH + idx] = nn;
        out[3 * BH + idx] = mn;
    }
}

// ================================ launch ====================================
extern "C" void kernel_launch(void* const* d_in, const int* in_sizes, int n_in,
                              void* d_out, int out_size) {
    const float* x    = (const float*)d_in[0];
    const float* h    = (const float*)d_in[1];
    const float* c    = (const float*)d_in[2];
    const float* n    = (const float*)d_in[3];
    const float* m    = (const float*)d_in[4];
    const float* Wx   = (const float*)d_in[5];
    const float* Wh   = (const float*)d_in[6];
    const float* bias = (const float*)d_in[7];
    float* out = (float*)d_out;

    pack_kernel<<<10240, 128>>>(x, h, Wx, Wh);

    cudaFuncSetAttribute(slstm_main, cudaFuncAttributeMaxDynamicSharedMemorySize,
                         SMEM_TOTAL);
    dim3 grid(16, 128);   // (nt, mt)
    slstm_main<<<grid, 512, SMEM_TOTAL>>>(c, n, m, bias, out);
}

// round 7
// speedup vs baseline: 8.0917x; 1.1505x over previous
#include <cuda_runtime.h>
#include <cuda_fp16.h>
#include <cstdint>
#include <math.h>

// ============================================================================
// sLSTM cell: gates = [x|h] @ [Wx|Wh]^T + b, exp-gate epilogue.
// fp16 2-term split GEMM (x16 @ (Whi + Wlo)^T, fp32 accum), mma.sync.m16n8k16.
// R7: 256-thread CTA, 128x128 tile, 96KB smem -> 2 CTAs/SM (two independent
//     barrier domains fill each other's wait/barrier bubbles). Warp tile
//     32x64; hi/lo MMA terms issued in separate passes.
// ============================================================================

#define BATCH 16384
#define HDIM  1024
#define NKT   64                         // 64 k-tiles of 32 over K=2048
#define APLANE 8192                      // one 128-row x 32-k fp16 plane
#define STAGE_BYTES (3 * APLANE)         // A | Whi | Wlo = 24576
#define STAGES 4
#define SMEM_TOTAL (STAGES * STAGE_BYTES)    // 98304 -> 2 CTAs/SM

// Scratch: A single fp16 plane per (mt,kt); W hi+lo per (nt,kt), gate-blocked.
__device__ __align__(16) __half g_Apack[(size_t)8192 * 4096]; // 67 MB
__device__ __align__(16) __half g_Wpack[(size_t)2048 * 8192]; // 33 MB

__device__ __forceinline__ uint32_t smem_u32(const void* p) {
    uint32_t a;
    asm("{ .reg .u64 t; cvta.to.shared.u64 t, %1; cvt.u32.u64 %0, t; }" : "=r"(a) : "l"(p));
    return a;
}

#define LDSM_X4(r, addr)                                                        \
    asm volatile("ldmatrix.sync.aligned.m8n8.x4.shared.b16 {%0,%1,%2,%3}, [%4];" \
                 : "=r"((r)[0]), "=r"((r)[1]), "=r"((r)[2]), "=r"((r)[3])       \
                 : "r"(addr))

#define MMA16816(d, a, b)                                                       \
    asm volatile("mma.sync.aligned.m16n8k16.row.col.f32.f16.f16.f32 "           \
                 "{%0,%1,%2,%3}, {%4,%5,%6,%7}, {%8,%9}, {%0,%1,%2,%3};"        \
                 : "+f"((d)[0]), "+f"((d)[1]), "+f"((d)[2]), "+f"((d)[3])       \
                 : "r"((a)[0]), "r"((a)[1]), "r"((a)[2]), "r"((a)[3]),          \
                   "r"((b)[0]), "r"((b)[1]))

#define CP_ASYNC16(dst, src) \
    asm volatile("cp.async.cg.shared.global [%0], [%1], 16;" :: "r"(dst), "l"(src))
#define CP_COMMIT() asm volatile("cp.async.commit_group;" ::: "memory")
#define CP_WAIT2()  asm volatile("cp.async.wait_group 2;" ::: "memory")

// swizzled byte offset within an 8KB plane for (row, 16B-chunk)
__device__ __forceinline__ uint32_t swz(int row, int ch) {
    return (uint32_t)(row * 64 + ((ch ^ ((row >> 1) & 3)) << 4));
}

// ============================== pack kernel (unchanged) =====================
__global__ __launch_bounds__(128) void pack_kernel(
    const float* __restrict__ x, const float* __restrict__ h,
    const float* __restrict__ Wx, const float* __restrict__ Wh)
{
    const int bt = blockIdx.x, t = threadIdx.x;
    const bool isA = bt < 8192;
    const int tile = isA ? bt : bt - 8192;
    const int kt = tile & 63;
    const int rt = tile >> 6;
    const float* src = (kt < 32) ? (isA ? x : Wx) : (isA ? h : Wh);
    const int kbase = (kt & 31) * 32;

    if (isA) {
        __half* dst = g_Apack + (size_t)tile * 4096;
        #pragma unroll
        for (int i = 0; i < 8; i++) {
            const int cc = i * 128 + t;
            const int r = cc >> 3, k4 = cc & 7;
            float4 v = *(const float4*)(src + (size_t)(rt * 128 + r) * 1024 + kbase + k4 * 4);
            __half2 p0 = __floats2half2_rn(v.x, v.y);
            __half2 p1 = __floats2half2_rn(v.z, v.w);
            *(uint2*)(dst + r * 32 + k4 * 4) =
                make_uint2(*(uint32_t*)&p0, *(uint32_t*)&p1);
        }
    } else {
        __half* dst = g_Wpack + (size_t)tile * 8192;
        #pragma unroll
        for (int i = 0; i < 8; i++) {
            const int cc = i * 128 + t;
            const int r = cc >> 3, k4 = cc & 7;
            const int grow = (r >> 5) * HDIM + rt * 32 + (r & 31);
            float4 v = *(const float4*)(src + (size_t)grow * 1024 + kbase + k4 * 4);
            float hx = __half2float(__float2half_rn(v.x));
            float hy = __half2float(__float2half_rn(v.y));
            float hz = __half2float(__float2half_rn(v.z));
            float hw = __half2float(__float2half_rn(v.w));
            __half2 h0 = __floats2half2_rn(hx, hy);
            __half2 h1 = __floats2half2_rn(hz, hw);
            __half2 l0 = __floats2half2_rn(v.x - hx, v.y - hy);
            __half2 l1 = __floats2half2_rn(v.z - hz, v.w - hw);
            const int eoff = r * 32 + k4 * 4;
            *(uint2*)(dst + eoff)        = make_uint2(*(uint32_t*)&h0, *(uint32_t*)&h1);
            *(uint2*)(dst + 4096 + eoff) = make_uint2(*(uint32_t*)&l0, *(uint32_t*)&l1);
        }
    }
}

// =============================== main kernel ================================
// 256 threads = 8 warps in 4(m) x 2(n) grid; warp (wm, wn) computes 32 x 64.
__global__ __launch_bounds__(256, 2) void slstm_main(
    const float* __restrict__ c_in, const float* __restrict__ n_in,
    const float* __restrict__ m_in, const float* __restrict__ bias,
    float* __restrict__ out)
{
    extern __shared__ char smraw[];
    const uint32_t sb = smem_u32(smraw);
    const int t = threadIdx.x, lane = t & 31, wid = t >> 5;
    const int nt = blockIdx.x, mt = blockIdx.y;
    const int wm = wid >> 1, wn = wid & 1;

    const char* Abase = (const char*)g_Apack + (size_t)(mt * 64) * 8192;
    const char* Wbase = (const char*)g_Wpack + (size_t)(nt * 64) * 16384;

    // --- stage loader: 3 planes x 512 chunks, 6 x 16B per thread ---
    auto load_stage = [&](int s, int kt) {
        const uint32_t d0 = sb + s * STAGE_BYTES;
        #pragma unroll
        for (int i = 0; i < 6; i++) {
            const int c = i * 256 + t;
            const int plane = c >> 9, w = c & 511;
            const int row = w >> 2, ch = w & 3;
            const char* src = (plane == 0)
                ? Abase + (size_t)kt * 8192 + w * 16
                : Wbase + (size_t)kt * 16384 + (size_t)(plane - 1) * 8192 + w * 16;
            CP_ASYNC16(d0 + plane * APLANE + swz(row, ch), src);
        }
    };

    // prologue: stages 0..2
    #pragma unroll
    for (int s = 0; s < 3; s++) { load_stage(s, s); CP_COMMIT(); }

    float acc[2][8][4];
    #pragma unroll
    for (int a = 0; a < 2; a++)
        #pragma unroll
        for (int b = 0; b < 8; b++)
            #pragma unroll
            for (int e = 0; e < 4; e++) acc[a][b][e] = 0.0f;

    int cs = 0, ls = 3;
    for (int kt = 0; kt < NKT; kt++) {
        CP_WAIT2();
        __syncthreads();
        if (kt + 3 < NKT) load_stage(ls, kt + 3);
        CP_COMMIT();
        if (++ls == STAGES) ls = 0;

        const uint32_t st = sb + cs * STAGE_BYTES;
        if (++cs == STAGES) cs = 0;

        #pragma unroll
        for (int ks = 0; ks < 2; ks++) {
            uint32_t afr[2][4], whi[4][4], wlo[4][4];
            #pragma unroll
            for (int tm = 0; tm < 2; tm++) {
                const int r = wm * 32 + tm * 16 + (lane & 15);
                const int ch = ks * 2 + (lane >> 4);
                LDSM_X4(afr[tm], st + swz(r, ch));
            }
            #pragma unroll
            for (int p = 0; p < 4; p++) {
                const int r = wn * 64 + p * 16 + ((lane >> 4) << 3) + (lane & 7);
                const int ch = ks * 2 + ((lane >> 3) & 1);
                const uint32_t a = st + APLANE + swz(r, ch);
                LDSM_X4(whi[p], a);
                LDSM_X4(wlo[p], a + APLANE);
            }
            // hi pass, then lo pass: same-acc dependent MMAs 8+ issues apart
            #pragma unroll
            for (int tm = 0; tm < 2; tm++)
                #pragma unroll
                for (int tn = 0; tn < 8; tn++)
                    MMA16816(acc[tm][tn], afr[tm], (&whi[tn >> 1][(tn & 1) * 2]));
            #pragma unroll
            for (int tm = 0; tm < 2; tm++)
                #pragma unroll
                for (int tn = 0; tn < 8; tn++)
                    MMA16816(acc[tm][tn], afr[tm], (&wlo[tn >> 1][(tn & 1) * 2]));
        }
    }

    // --- exchange accumulators through smem: [128][132] fp32 ---
    __syncthreads();
    float* smf = (float*)smraw;
    #pragma unroll
    for (int tm = 0; tm < 2; tm++)
        #pragma unroll
        for (int tn = 0; tn < 8; tn++) {
            const int row = wm * 32 + tm * 16 + (lane >> 2);
            const int col = wn * 64 + tn * 8 + (lane & 3) * 2;
            smf[row * 132 + col]           = acc[tm][tn][0];
            smf[row * 132 + col + 1]       = acc[tm][tn][1];
            smf[(row + 8) * 132 + col]     = acc[tm][tn][2];
            smf[(row + 8) * 132 + col + 1] = acc[tm][tn][3];
        }
    __syncthreads();

    // --- fused sLSTM epilogue: thread -> (16 rows, 1 hidden col) ---
    const int jj = t & 31;
    const int rb = (t >> 5) * 16;
    const int jcol = nt * 32 + jj;
    const float b_i = bias[jcol];
    const float b_f = bias[HDIM + jcol];
    const float b_z = bias[2 * HDIM + jcol];
    const float b_o = bias[3 * HDIM + jcol];
    const size_t BH = (size_t)BATCH * HDIM;

    #pragma unroll
    for (int rr = 0; rr < 16; rr++) {
        const int row = rb + rr;
        const size_t idx = (size_t)(mt * 128 + row) * HDIM + jcol;
        const float iv = smf[row * 132 + 0 * 32 + jj] + b_i;
        const float fv = smf[row * 132 + 1 * 32 + jj] + b_f;
        const float zv = smf[row * 132 + 2 * 32 + jj] + b_z;
        const float ov = smf[row * 132 + 3 * 32 + jj] + b_o;
        const float mo = m_in[idx];
        const float mn = fmaxf(fv + mo, iv);
        const float fg = __expf(fv + mo - mn);
        const float ig = __expf(iv - mn);
        const float zg = tanhf(zv);
        const float og = 1.0f / (1.0f + __expf(-ov));
        const float cn = fg * c_in[idx] + ig * zg;
        const float nn = fg * n_in[idx] + ig;
        const float hn = og * (cn / fmaxf(fabsf(nn), 1.0f));
        out[idx]          = hn;
        out[BH + idx]     = cn;
        out[2 * BH + idx] = nn;
        out[3 * BH + idx] = mn;
    }
}

// ================================ launch ====================================
extern "C" void kernel_launch(void* const* d_in, const int* in_sizes, int n_in,
                              void* d_out, int out_size) {
    const float* x    = (const float*)d_in[0];
    const float* h    = (const float*)d_in[1];
    const float* c    = (const float*)d_in[2];
    const float* n    = (const float*)d_in[3];
    const float* m    = (const float*)d_in[4];
    const float* Wx   = (const float*)d_in[5];
    const float* Wh   = (const float*)d_in[6];
    const float* bias = (const float*)d_in[7];
    float* out = (float*)d_out;

    pack_kernel<<<10240, 128>>>(x, h, Wx, Wh);

    cudaFuncSetAttribute(slstm_main, cudaFuncAttributeMaxDynamicSharedMemorySize,
                         SMEM_TOTAL);
    dim3 grid(32, 128);   // (nt, mt)
    slstm_main<<<grid, 256, SMEM_TOTAL>>>(c, n, m, bias, out);
}

// round 8
// speedup vs baseline: 8.5202x; 1.0529x over previous
#include <cuda_runtime.h>
#include <cuda_fp16.h>
#include <cstdint>
#include <math.h>

// ============================================================================
// sLSTM cell: gates = [x|h] @ [Wx|Wh]^T + b, exp-gate epilogue.
// fp16 2-term split GEMM (x16 @ (Whi + Wlo)^T, fp32 accum), mma.sync.m16n8k16.
// R8: 2 ktiles consumed per wait+sync (32 barriers instead of 64). 4 stages,
//     96KB smem, 2 CTAs/SM, warp tile 32x64, hi/lo MMA passes separated.
// ============================================================================

#define BATCH 16384
#define HDIM  1024
#define NKT   64                         // 64 k-tiles of 32 over K=2048
#define APLANE 8192                      // one 128-row x 32-k fp16 plane
#define STAGE_BYTES (3 * APLANE)         // A | Whi | Wlo = 24576
#define STAGES 4
#define SMEM_TOTAL (STAGES * STAGE_BYTES)    // 98304 -> 2 CTAs/SM

// Scratch: A single fp16 plane per (mt,kt); W hi+lo per (nt,kt), gate-blocked.
__device__ __align__(16) __half g_Apack[(size_t)8192 * 4096]; // 67 MB
__device__ __align__(16) __half g_Wpack[(size_t)2048 * 8192]; // 33 MB

__device__ __forceinline__ uint32_t smem_u32(const void* p) {
    uint32_t a;
    asm("{ .reg .u64 t; cvta.to.shared.u64 t, %1; cvt.u32.u64 %0, t; }" : "=r"(a) : "l"(p));
    return a;
}

#define LDSM_X4(r, addr)                                                        \
    asm volatile("ldmatrix.sync.aligned.m8n8.x4.shared.b16 {%0,%1,%2,%3}, [%4];" \
                 : "=r"((r)[0]), "=r"((r)[1]), "=r"((r)[2]), "=r"((r)[3])       \
                 : "r"(addr))

#define MMA16816(d, a, b)                                                       \
    asm volatile("mma.sync.aligned.m16n8k16.row.col.f32.f16.f16.f32 "           \
                 "{%0,%1,%2,%3}, {%4,%5,%6,%7}, {%8,%9}, {%0,%1,%2,%3};"        \
                 : "+f"((d)[0]), "+f"((d)[1]), "+f"((d)[2]), "+f"((d)[3])       \
                 : "r"((a)[0]), "r"((a)[1]), "r"((a)[2]), "r"((a)[3]),          \
                   "r"((b)[0]), "r"((b)[1]))

#define CP_ASYNC16(dst, src) \
    asm volatile("cp.async.cg.shared.global [%0], [%1], 16;" :: "r"(dst), "l"(src))
#define CP_COMMIT() asm volatile("cp.async.commit_group;" ::: "memory")
#define CP_WAIT2()  asm volatile("cp.async.wait_group 2;" ::: "memory")

// swizzled byte offset within an 8KB plane for (row, 16B-chunk)
__device__ __forceinline__ uint32_t swz(int row, int ch) {
    return (uint32_t)(row * 64 + ((ch ^ ((row >> 1) & 3)) << 4));
}

// ============================== pack kernel (unchanged) =====================
__global__ __launch_bounds__(128) void pack_kernel(
    const float* __restrict__ x, const float* __restrict__ h,
    const float* __restrict__ Wx, const float* __restrict__ Wh)
{
    const int bt = blockIdx.x, t = threadIdx.x;
    const bool isA = bt < 8192;
    const int tile = isA ? bt : bt - 8192;
    const int kt = tile & 63;
    const int rt = tile >> 6;
    const float* src = (kt < 32) ? (isA ? x : Wx) : (isA ? h : Wh);
    const int kbase = (kt & 31) * 32;

    if (isA) {
        __half* dst = g_Apack + (size_t)tile * 4096;
        #pragma unroll
        for (int i = 0; i < 8; i++) {
            const int cc = i * 128 + t;
            const int r = cc >> 3, k4 = cc & 7;
            float4 v = *(const float4*)(src + (size_t)(rt * 128 + r) * 1024 + kbase + k4 * 4);
            __half2 p0 = __floats2half2_rn(v.x, v.y);
            __half2 p1 = __floats2half2_rn(v.z, v.w);
            *(uint2*)(dst + r * 32 + k4 * 4) =
                make_uint2(*(uint32_t*)&p0, *(uint32_t*)&p1);
        }
    } else {
        __half* dst = g_Wpack + (size_t)tile * 8192;
        #pragma unroll
        for (int i = 0; i < 8; i++) {
            const int cc = i * 128 + t;
            const int r = cc >> 3, k4 = cc & 7;
            const int grow = (r >> 5) * HDIM + rt * 32 + (r & 31);
            float4 v = *(const float4*)(src + (size_t)grow * 1024 + kbase + k4 * 4);
            float hx = __half2float(__float2half_rn(v.x));
            float hy = __half2float(__float2half_rn(v.y));
            float hz = __half2float(__float2half_rn(v.z));
            float hw = __half2float(__float2half_rn(v.w));
            __half2 h0 = __floats2half2_rn(hx, hy);
            __half2 h1 = __floats2half2_rn(hz, hw);
            __half2 l0 = __floats2half2_rn(v.x - hx, v.y - hy);
            __half2 l1 = __floats2half2_rn(v.z - hz, v.w - hw);
            const int eoff = r * 32 + k4 * 4;
            *(uint2*)(dst + eoff)        = make_uint2(*(uint32_t*)&h0, *(uint32_t*)&h1);
            *(uint2*)(dst + 4096 + eoff) = make_uint2(*(uint32_t*)&l0, *(uint32_t*)&l1);
        }
    }
}

// =============================== main kernel ================================
// 256 threads = 8 warps in 4(m) x 2(n) grid; warp (wm, wn) computes 32 x 64.
__global__ __launch_bounds__(256, 2) void slstm_main(
    const float* __restrict__ c_in, const float* __restrict__ n_in,
    const float* __restrict__ m_in, const float* __restrict__ bias,
    float* __restrict__ out)
{
    extern __shared__ char smraw[];
    const uint32_t sb = smem_u32(smraw);
    const int t = threadIdx.x, lane = t & 31, wid = t >> 5;
    const int nt = blockIdx.x, mt = blockIdx.y;
    const int wm = wid >> 1, wn = wid & 1;

    const char* Abase = (const char*)g_Apack + (size_t)(mt * 64) * 8192;
    const char* Wbase = (const char*)g_Wpack + (size_t)(nt * 64) * 16384;

    // --- stage loader: 3 planes x 512 chunks, 6 x 16B per thread ---
    auto load_stage = [&](int s, int kt) {
        const uint32_t d0 = sb + s * STAGE_BYTES;
        #pragma unroll
        for (int i = 0; i < 6; i++) {
            const int c = i * 256 + t;
            const int plane = c >> 9, w = c & 511;
            const int row = w >> 2, ch = w & 3;
            const char* src = (plane == 0)
                ? Abase + (size_t)kt * 8192 + w * 16
                : Wbase + (size_t)kt * 16384 + (size_t)(plane - 1) * 8192 + w * 16;
            CP_ASYNC16(d0 + plane * APLANE + swz(row, ch), src);
        }
    };

    // --- one ktile of MMA work from a given stage ---
    float acc[2][8][4];
    #pragma unroll
    for (int a = 0; a < 2; a++)
        #pragma unroll
        for (int b = 0; b < 8; b++)
            #pragma unroll
            for (int e = 0; e < 4; e++) acc[a][b][e] = 0.0f;

    auto compute_stage = [&](int s) {
        const uint32_t st = sb + s * STAGE_BYTES;
        #pragma unroll
        for (int ks = 0; ks < 2; ks++) {
            uint32_t afr[2][4], whi[4][4], wlo[4][4];
            #pragma unroll
            for (int tm = 0; tm < 2; tm++) {
                const int r = wm * 32 + tm * 16 + (lane & 15);
                const int ch = ks * 2 + (lane >> 4);
                LDSM_X4(afr[tm], st + swz(r, ch));
            }
            #pragma unroll
            for (int p = 0; p < 4; p++) {
                const int r = wn * 64 + p * 16 + ((lane >> 4) << 3) + (lane & 7);
                const int ch = ks * 2 + ((lane >> 3) & 1);
                const uint32_t a = st + APLANE + swz(r, ch);
                LDSM_X4(whi[p], a);
                LDSM_X4(wlo[p], a + APLANE);
            }
            #pragma unroll
            for (int tm = 0; tm < 2; tm++)
                #pragma unroll
                for (int tn = 0; tn < 8; tn++)
                    MMA16816(acc[tm][tn], afr[tm], (&whi[tn >> 1][(tn & 1) * 2]));
            #pragma unroll
            for (int tm = 0; tm < 2; tm++)
                #pragma unroll
                for (int tn = 0; tn < 8; tn++)
                    MMA16816(acc[tm][tn], afr[tm], (&wlo[tn >> 1][(tn & 1) * 2]));
        }
    };

    // prologue: load stages 0,1 for ktiles 0,1 (one commit group each)
    load_stage(0, 0); CP_COMMIT();
    load_stage(1, 1); CP_COMMIT();

    // main loop: 32 iterations, 2 ktiles each.
    // iter i: computes stage pair P_i = {(2i)%4, (2i+1)%4}; first loads pair
    // P_{i+1} (which occupies the stages consumed in iter i-1) for kt+2, kt+3.
    for (int kt = 0; kt < NKT; kt += 2) {
        __syncthreads();                    // prev iteration's reads complete
        const int sl = (kt + 2) & 3;        // load-pair base stage
        if (kt + 2 < NKT) load_stage(sl, kt + 2);
        CP_COMMIT();
        if (kt + 3 < NKT) load_stage(sl ^ 1, kt + 3);
        CP_COMMIT();
        CP_WAIT2();                         // groups for this pair complete
        __syncthreads();                    // publish smem to all warps
        compute_stage(kt & 3);
        compute_stage((kt + 1) & 3);
    }

    // --- exchange accumulators through smem: [128][132] fp32 ---
    __syncthreads();
    float* smf = (float*)smraw;
    #pragma unroll
    for (int tm = 0; tm < 2; tm++)
        #pragma unroll
        for (int tn = 0; tn < 8; tn++) {
            const int row = wm * 32 + tm * 16 + (lane >> 2);
            const int col = wn * 64 + tn * 8 + (lane & 3) * 2;
            smf[row * 132 + col]           = acc[tm][tn][0];
            smf[row * 132 + col + 1]       = acc[tm][tn][1];
            smf[(row + 8) * 132 + col]     = acc[tm][tn][2];
            smf[(row + 8) * 132 + col + 1] = acc[tm][tn][3];
        }
    __syncthreads();

    // --- fused sLSTM epilogue: thread -> (16 rows, 1 hidden col) ---
    const int jj = t & 31;
    const int rb = (t >> 5) * 16;
    const int jcol = nt * 32 + jj;
    const float b_i = bias[jcol];
    const float b_f = bias[HDIM + jcol];
    const float b_z = bias[2 * HDIM + jcol];
    const float b_o = bias[3 * HDIM + jcol];
    const size_t BH = (size_t)BATCH * HDIM;

    #pragma unroll
    for (int rr = 0; rr < 16; rr++) {
        const int row = rb + rr;
        const size_t idx = (size_t)(mt * 128 + row) * HDIM + jcol;
        const float iv = smf[row * 132 + 0 * 32 + jj] + b_i;
        const float fv = smf[row * 132 + 1 * 32 + jj] + b_f;
        const float zv = smf[row * 132 + 2 * 32 + jj] + b_z;
        const float ov = smf[row * 132 + 3 * 32 + jj] + b_o;
        const float mo = m_in[idx];
        const float mn = fmaxf(fv + mo, iv);
        const float fg = __expf(fv + mo - mn);
        const float ig = __expf(iv - mn);
        const float zg = tanhf(zv);
        const float og = 1.0f / (1.0f + __expf(-ov));
        const float cn = fg * c_in[idx] + ig * zg;
        const float nn = fg * n_in[idx] + ig;
        const float hn = og * (cn / fmaxf(fabsf(nn), 1.0f));
        out[idx]          = hn;
        out[BH + idx]     = cn;
        out[2 * BH + idx] = nn;
        out[3 * BH + idx] = mn;
    }
}

// ================================ launch ====================================
extern "C" void kernel_launch(void* const* d_in, const int* in_sizes, int n_in,
                              void* d_out, int out_size) {
    const float* x    = (const float*)d_in[0];
    const float* h    = (const float*)d_in[1];
    const float* c    = (const float*)d_in[2];
    const float* n    = (const float*)d_in[3];
    const float* m    = (const float*)d_in[4];
    const float* Wx   = (const float*)d_in[5];
    const float* Wh   = (const float*)d_in[6];
    const float* bias = (const float*)d_in[7];
    float* out = (float*)d_out;

    pack_kernel<<<10240, 128>>>(x, h, Wx, Wh);

    cudaFuncSetAttribute(slstm_main, cudaFuncAttributeMaxDynamicSharedMemorySize,
                         SMEM_TOTAL);
    dim3 grid(32, 128);   // (nt, mt)
    slstm_main<<<grid, 256, SMEM_TOTAL>>>(c, n, m, bias, out);
}

// round 9
// speedup vs baseline: 12.7778x; 1.4997x over previous
#include <cuda_runtime.h>
#include <cuda_fp16.h>
#include <cstdint>
#include <math.h>

// ============================================================================
// sLSTM cell: gates = [x|h] @ [Wx|Wh]^T + b, exp-gate epilogue.
// R9: single-pass fp16 GEMM (x16 @ W16^T, fp32 accum) via mma.sync.m16n8k16.
//     Activation + weight fp16 rounding are independent ~2^-11 errors ->
//     rel_err ~3.3e-4 (3x margin under 1e-3), HMMA count halved vs R8.
//     16KB stages x 6, 2 CTAs/SM, pair-wise ktile loop (1 sync / 2 ktiles).
// ============================================================================

#define BATCH 16384
#define HDIM  1024
#define NKT   64                         // 64 k-tiles of 32 over K=2048
#define APLANE 8192                      // one 128-row x 32-k fp16 plane
#define STAGE_BYTES (2 * APLANE)         // A | W = 16384
#define STAGES 6
#define SMEM_TOTAL (STAGES * STAGE_BYTES)    // 98304 -> 2 CTAs/SM

// Scratch: one fp16 plane per (mt,kt) A-tile and per (nt,kt) W-tile.
__device__ __align__(16) __half g_Apack[(size_t)8192 * 4096]; // 67 MB
__device__ __align__(16) __half g_Wpack[(size_t)2048 * 4096]; // 17 MB

__device__ __forceinline__ uint32_t smem_u32(const void* p) {
    uint32_t a;
    asm("{ .reg .u64 t; cvta.to.shared.u64 t, %1; cvt.u32.u64 %0, t; }" : "=r"(a) : "l"(p));
    return a;
}

#define LDSM_X4(r, addr)                                                        \
    asm volatile("ldmatrix.sync.aligned.m8n8.x4.shared.b16 {%0,%1,%2,%3}, [%4];" \
                 : "=r"((r)[0]), "=r"((r)[1]), "=r"((r)[2]), "=r"((r)[3])       \
                 : "r"(addr))

#define MMA16816(d, a, b)                                                       \
    asm volatile("mma.sync.aligned.m16n8k16.row.col.f32.f16.f16.f32 "           \
                 "{%0,%1,%2,%3}, {%4,%5,%6,%7}, {%8,%9}, {%0,%1,%2,%3};"        \
                 : "+f"((d)[0]), "+f"((d)[1]), "+f"((d)[2]), "+f"((d)[3])       \
                 : "r"((a)[0]), "r"((a)[1]), "r"((a)[2]), "r"((a)[3]),          \
                   "r"((b)[0]), "r"((b)[1]))

#define CP_ASYNC16(dst, src) \
    asm volatile("cp.async.cg.shared.global [%0], [%1], 16;" :: "r"(dst), "l"(src))
#define CP_COMMIT() asm volatile("cp.async.commit_group;" ::: "memory")
#define CP_WAIT4()  asm volatile("cp.async.wait_group 4;" ::: "memory")

// swizzled byte offset within an 8KB plane for (row, 16B-chunk)
__device__ __forceinline__ uint32_t swz(int row, int ch) {
    return (uint32_t)(row * 64 + ((ch ^ ((row >> 1) & 3)) << 4));
}

// ============================== pack kernel =================================
// A tiles (blocks [0,8192)): 128 batch rows x 32 k -> fp16 plane.
// W tiles (blocks [8192,10240)): gate-blocked rows -> single fp16 plane.
__global__ __launch_bounds__(128) void pack_kernel(
    const float* __restrict__ x, const float* __restrict__ h,
    const float* __restrict__ Wx, const float* __restrict__ Wh)
{
    const int bt = blockIdx.x, t = threadIdx.x;
    const bool isA = bt < 8192;
    const int tile = isA ? bt : bt - 8192;
    const int kt = tile & 63;
    const int rt = tile >> 6;
    const float* src = (kt < 32) ? (isA ? x : Wx) : (isA ? h : Wh);
    const int kbase = (kt & 31) * 32;
    __half* dst = (isA ? g_Apack : g_Wpack) + (size_t)tile * 4096;

    #pragma unroll
    for (int i = 0; i < 8; i++) {
        const int cc = i * 128 + t;
        const int r = cc >> 3, k4 = cc & 7;
        const int grow = isA ? (rt * 128 + r)
                             : ((r >> 5) * HDIM + rt * 32 + (r & 31));
        float4 v = *(const float4*)(src + (size_t)grow * 1024 + kbase + k4 * 4);
        __half2 p0 = __floats2half2_rn(v.x, v.y);
        __half2 p1 = __floats2half2_rn(v.z, v.w);
        *(uint2*)(dst + r * 32 + k4 * 4) =
            make_uint2(*(uint32_t*)&p0, *(uint32_t*)&p1);
    }
}

// =============================== main kernel ================================
// 256 threads = 8 warps in 4(m) x 2(n) grid; warp (wm, wn) computes 32 x 64.
__global__ __launch_bounds__(256, 2) void slstm_main(
    const float* __restrict__ c_in, const float* __restrict__ n_in,
    const float* __restrict__ m_in, const float* __restrict__ bias,
    float* __restrict__ out)
{
    extern __shared__ char smraw[];
    const uint32_t sb = smem_u32(smraw);
    const int t = threadIdx.x, lane = t & 31, wid = t >> 5;
    const int nt = blockIdx.x, mt = blockIdx.y;
    const int wm = wid >> 1, wn = wid & 1;

    const char* Abase = (const char*)g_Apack + (size_t)(mt * 64) * 8192;
    const char* Wbase = (const char*)g_Wpack + (size_t)(nt * 64) * 8192;

    // --- stage loader: 2 planes x 512 chunks, 4 x 16B per thread ---
    auto load_stage = [&](int s, int kt) {
        const uint32_t d0 = sb + s * STAGE_BYTES;
        #pragma unroll
        for (int i = 0; i < 4; i++) {
            const int c = i * 256 + t;
            const int plane = c >> 9, w = c & 511;
            const int row = w >> 2, ch = w & 3;
            const char* src = (plane == 0)
                ? Abase + (size_t)kt * 8192 + w * 16
                : Wbase + (size_t)kt * 8192 + w * 16;
            CP_ASYNC16(d0 + plane * APLANE + swz(row, ch), src);
        }
    };

    float acc[2][8][4];
    #pragma unroll
    for (int a = 0; a < 2; a++)
        #pragma unroll
        for (int b = 0; b < 8; b++)
            #pragma unroll
            for (int e = 0; e < 4; e++) acc[a][b][e] = 0.0f;

    auto compute_stage = [&](int s) {
        const uint32_t st = sb + s * STAGE_BYTES;
        #pragma unroll
        for (int ks = 0; ks < 2; ks++) {
            uint32_t afr[2][4], wfr[4][4];
            #pragma unroll
            for (int tm = 0; tm < 2; tm++) {
                const int r = wm * 32 + tm * 16 + (lane & 15);
                const int ch = ks * 2 + (lane >> 4);
                LDSM_X4(afr[tm], st + swz(r, ch));
            }
            #pragma unroll
            for (int p = 0; p < 4; p++) {
                const int r = wn * 64 + p * 16 + ((lane >> 4) << 3) + (lane & 7);
                const int ch = ks * 2 + ((lane >> 3) & 1);
                LDSM_X4(wfr[p], st + APLANE + swz(r, ch));
            }
            #pragma unroll
            for (int tm = 0; tm < 2; tm++)
                #pragma unroll
                for (int tn = 0; tn < 8; tn++)
                    MMA16816(acc[tm][tn], afr[tm], (&wfr[tn >> 1][(tn & 1) * 2]));
        }
    };

    // prologue: stages 0..3 for ktiles 0..3 (one commit group each)
    #pragma unroll
    for (int s = 0; s < 4; s++) { load_stage(s, s); CP_COMMIT(); }

    // main loop: 32 iterations, 2 ktiles each; prefetch 4 ktiles ahead.
    for (int kt = 0; kt < NKT; kt += 2) {
        __syncthreads();                 // stage (kt+4)%6 was consumed @ kt-2
        if (kt + 4 < NKT) load_stage((kt + 4) % STAGES, kt + 4);
        CP_COMMIT();
        if (kt + 5 < NKT) load_stage((kt + 5) % STAGES, kt + 5);
        CP_COMMIT();
        CP_WAIT4();                      // kt, kt+1 groups complete
        __syncthreads();
        compute_stage(kt % STAGES);
        compute_stage((kt + 1) % STAGES);
    }

    // --- exchange accumulators through smem: [128][132] fp32 ---
    __syncthreads();
    float* smf = (float*)smraw;
    #pragma unroll
    for (int tm = 0; tm < 2; tm++)
        #pragma unroll
        for (int tn = 0; tn < 8; tn++) {
            const int row = wm * 32 + tm * 16 + (lane >> 2);
            const int col = wn * 64 + tn * 8 + (lane & 3) * 2;
            smf[row * 132 + col]           = acc[tm][tn][0];
            smf[row * 132 + col + 1]       = acc[tm][tn][1];
            smf[(row + 8) * 132 + col]     = acc[tm][tn][2];
            smf[(row + 8) * 132 + col + 1] = acc[tm][tn][3];
        }
    __syncthreads();

    // --- fused sLSTM epilogue: thread -> (16 rows, 1 hidden col) ---
    const int jj = t & 31;
    const int rb = (t >> 5) * 16;
    const int jcol = nt * 32 + jj;
    const float b_i = bias[jcol];
    const float b_f = bias[HDIM + jcol];
    const float b_z = bias[2 * HDIM + jcol];
    const float b_o = bias[3 * HDIM + jcol];
    const size_t BH = (size_t)BATCH * HDIM;

    #pragma unroll
    for (int rr = 0; rr < 16; rr++) {
        const int row = rb + rr;
        const size_t idx = (size_t)(mt * 128 + row) * HDIM + jcol;
        const float iv = smf[row * 132 + 0 * 32 + jj] + b_i;
        const float fv = smf[row * 132 + 1 * 32 + jj] + b_f;
        const float zv = smf[row * 132 + 2 * 32 + jj] + b_z;
        const float ov = smf[row * 132 + 3 * 32 + jj] + b_o;
        const float mo = m_in[idx];
        const float mn = fmaxf(fv + mo, iv);
        const float fg = __expf(fv + mo - mn);
        const float ig = __expf(iv - mn);
        const float zg = tanhf(zv);
        const float og = 1.0f / (1.0f + __expf(-ov));
        const float cn = fg * c_in[idx] + ig * zg;
        const float nn = fg * n_in[idx] + ig;
        const float hn = og * (cn / fmaxf(fabsf(nn), 1.0f));
        out[idx]          = hn;
        out[BH + idx]     = cn;
        out[2 * BH + idx] = nn;
        out[3 * BH + idx] = mn;
    }
}

// ================================ launch ====================================
extern "C" void kernel_launch(void* const* d_in, const int* in_sizes, int n_in,
                              void* d_out, int out_size) {
    const float* x    = (const float*)d_in[0];
    const float* h    = (const float*)d_in[1];
    const float* c    = (const float*)d_in[2];
    const float* n    = (const float*)d_in[3];
    const float* m    = (const float*)d_in[4];
    const float* Wx   = (const float*)d_in[5];
    const float* Wh   = (const float*)d_in[6];
    const float* bias = (const float*)d_in[7];
    float* out = (float*)d_out;

    pack_kernel<<<10240, 128>>>(x, h, Wx, Wh);

    cudaFuncSetAttribute(slstm_main, cudaFuncAttributeMaxDynamicSharedMemorySize,
                         SMEM_TOTAL);
    dim3 grid(32, 128);   // (nt, mt)
    slstm_main<<<grid, 256, SMEM_TOTAL>>>(c, n, m, bias, out);
}

// round 10
// speedup vs baseline: 12.9917x; 1.0167x over previous
#include <cuda_runtime.h>
#include <cuda_fp16.h>
#include <cstdint>
#include <math.h>

// ============================================================================
// sLSTM cell: gates = [x|h] @ [Wx|Wh]^T + b, exp-gate epilogue.
// R10: single-pass fp16 GEMM (x16 @ W16^T, fp32 accum), mma.sync.m16n8k16.
//      3 pair-slot pipeline (6 x 16KB stages): ONE __syncthreads per 2 ktiles
//      (32 syncs total). 2 CTAs/SM. Layouts/epilogue identical to R9.
// ============================================================================

#define BATCH 16384
#define HDIM  1024
#define NKT   64                         // 64 k-tiles of 32 over K=2048
#define APLANE 8192                      // one 128-row x 32-k fp16 plane
#define STAGE_BYTES (2 * APLANE)         // A | W = 16384
#define STAGES 6
#define SMEM_TOTAL (STAGES * STAGE_BYTES)    // 98304 -> 2 CTAs/SM

// Scratch: one fp16 plane per (mt,kt) A-tile and per (nt,kt) W-tile.
__device__ __align__(16) __half g_Apack[(size_t)8192 * 4096]; // 67 MB
__device__ __align__(16) __half g_Wpack[(size_t)2048 * 4096]; // 17 MB

__device__ __forceinline__ uint32_t smem_u32(const void* p) {
    uint32_t a;
    asm("{ .reg .u64 t; cvta.to.shared.u64 t, %1; cvt.u32.u64 %0, t; }" : "=r"(a) : "l"(p));
    return a;
}

#define LDSM_X4(r, addr)                                                        \
    asm volatile("ldmatrix.sync.aligned.m8n8.x4.shared.b16 {%0,%1,%2,%3}, [%4];" \
                 : "=r"((r)[0]), "=r"((r)[1]), "=r"((r)[2]), "=r"((r)[3])       \
                 : "r"(addr))

#define MMA16816(d, a, b)                                                       \
    asm volatile("mma.sync.aligned.m16n8k16.row.col.f32.f16.f16.f32 "           \
                 "{%0,%1,%2,%3}, {%4,%5,%6,%7}, {%8,%9}, {%0,%1,%2,%3};"        \
                 : "+f"((d)[0]), "+f"((d)[1]), "+f"((d)[2]), "+f"((d)[3])       \
                 : "r"((a)[0]), "r"((a)[1]), "r"((a)[2]), "r"((a)[3]),          \
                   "r"((b)[0]), "r"((b)[1]))

#define CP_ASYNC16(dst, src) \
    asm volatile("cp.async.cg.shared.global [%0], [%1], 16;" :: "r"(dst), "l"(src))
#define CP_COMMIT() asm volatile("cp.async.commit_group;" ::: "memory")
#define CP_WAIT0()  asm volatile("cp.async.wait_group 0;" ::: "memory")
#define CP_WAIT1()  asm volatile("cp.async.wait_group 1;" ::: "memory")

// swizzled byte offset within an 8KB plane for (row, 16B-chunk)
__device__ __forceinline__ uint32_t swz(int row, int ch) {
    return (uint32_t)(row * 64 + ((ch ^ ((row >> 1) & 3)) << 4));
}

// ============================== pack kernel =================================
__global__ __launch_bounds__(128) void pack_kernel(
    const float* __restrict__ x, const float* __restrict__ h,
    const float* __restrict__ Wx, const float* __restrict__ Wh)
{
    const int bt = blockIdx.x, t = threadIdx.x;
    const bool isA = bt < 8192;
    const int tile = isA ? bt : bt - 8192;
    const int kt = tile & 63;
    const int rt = tile >> 6;
    const float* src = (kt < 32) ? (isA ? x : Wx) : (isA ? h : Wh);
    const int kbase = (kt & 31) * 32;
    __half* dst = (isA ? g_Apack : g_Wpack) + (size_t)tile * 4096;

    #pragma unroll
    for (int i = 0; i < 8; i++) {
        const int cc = i * 128 + t;
        const int r = cc >> 3, k4 = cc & 7;
        const int grow = isA ? (rt * 128 + r)
                             : ((r >> 5) * HDIM + rt * 32 + (r & 31));
        float4 v = *(const float4*)(src + (size_t)grow * 1024 + kbase + k4 * 4);
        __half2 p0 = __floats2half2_rn(v.x, v.y);
        __half2 p1 = __floats2half2_rn(v.z, v.w);
        *(uint2*)(dst + r * 32 + k4 * 4) =
            make_uint2(*(uint32_t*)&p0, *(uint32_t*)&p1);
    }
}

// =============================== main kernel ================================
// 256 threads = 8 warps in 4(m) x 2(n) grid; warp (wm, wn) computes 32 x 64.
__global__ __launch_bounds__(256, 2) void slstm_main(
    const float* __restrict__ c_in, const float* __restrict__ n_in,
    const float* __restrict__ m_in, const float* __restrict__ bias,
    float* __restrict__ out)
{
    extern __shared__ char smraw[];
    const uint32_t sb = smem_u32(smraw);
    const int t = threadIdx.x, lane = t & 31, wid = t >> 5;
    const int nt = blockIdx.x, mt = blockIdx.y;
    const int wm = wid >> 1, wn = wid & 1;

    const char* Abase = (const char*)g_Apack + (size_t)(mt * 64) * 8192;
    const char* Wbase = (const char*)g_Wpack + (size_t)(nt * 64) * 8192;

    // --- stage loader: 2 planes x 512 chunks, 4 x 16B per thread ---
    auto load_stage = [&](int s, int kt) {
        const uint32_t d0 = sb + s * STAGE_BYTES;
        #pragma unroll
        for (int i = 0; i < 4; i++) {
            const int c = i * 256 + t;
            const int plane = c >> 9, w = c & 511;
            const int row = w >> 2, ch = w & 3;
            const char* src = (plane == 0)
                ? Abase + (size_t)kt * 8192 + w * 16
                : Wbase + (size_t)kt * 8192 + w * 16;
            CP_ASYNC16(d0 + plane * APLANE + swz(row, ch), src);
        }
    };

    float acc[2][8][4];
    #pragma unroll
    for (int a = 0; a < 2; a++)
        #pragma unroll
        for (int b = 0; b < 8; b++)
            #pragma unroll
            for (int e = 0; e < 4; e++) acc[a][b][e] = 0.0f;

    auto compute_stage = [&](int s) {
        const uint32_t st = sb + s * STAGE_BYTES;
        #pragma unroll
        for (int ks = 0; ks < 2; ks++) {
            uint32_t afr[2][4], wfr[4][4];
            #pragma unroll
            for (int tm = 0; tm < 2; tm++) {
                const int r = wm * 32 + tm * 16 + (lane & 15);
                const int ch = ks * 2 + (lane >> 4);
                LDSM_X4(afr[tm], st + swz(r, ch));
            }
            #pragma unroll
            for (int p = 0; p < 4; p++) {
                const int r = wn * 64 + p * 16 + ((lane >> 4) << 3) + (lane & 7);
                const int ch = ks * 2 + ((lane >> 3) & 1);
                LDSM_X4(wfr[p], st + APLANE + swz(r, ch));
            }
            #pragma unroll
            for (int tm = 0; tm < 2; tm++)
                #pragma unroll
                for (int tn = 0; tn < 8; tn++)
                    MMA16816(acc[tm][tn], afr[tm], (&wfr[tn >> 1][(tn & 1) * 2]));
        }
    };

    // prologue: pair 0 (ktiles 0,1 -> stages 0,1), pair 1 (2,3 -> 2,3);
    // one commit group per pair.
    load_stage(0, 0); load_stage(1, 1); CP_COMMIT();
    load_stage(2, 2); load_stage(3, 3); CP_COMMIT();

    // main loop: 32 iterations, one pair (2 ktiles) each, ONE sync per pair.
    // Pair p lives in slot p%3 (stages 2*(p%3), 2*(p%3)+1).
    // At iter p: wait(pair p data), sync (also certifies pair p-1 computed by
    // all warps), load pair p+2 into slot (p+2)%3 == (p-1)%3 (now free),
    // compute pair p.
    for (int kt = 0; kt < NKT; kt += 2) {
        if (kt + 2 >= NKT) { CP_WAIT0(); } else { CP_WAIT1(); }
        __syncthreads();
        if (kt + 4 < NKT) {
            const int slot = ((kt + 4) >> 1) % 3;
            load_stage(2 * slot,     kt + 4);
            load_stage(2 * slot + 1, kt + 5);
            CP_COMMIT();
        }
        const int cslot = (kt >> 1) % 3;
        compute_stage(2 * cslot);
        compute_stage(2 * cslot + 1);
    }

    // --- exchange accumulators through smem: [128][132] fp32 ---
    __syncthreads();
    float* smf = (float*)smraw;
    #pragma unroll
    for (int tm = 0; tm < 2; tm++)
        #pragma unroll
        for (int tn = 0; tn < 8; tn++) {
            const int row = wm * 32 + tm * 16 + (lane >> 2);
            const int col = wn * 64 + tn * 8 + (lane & 3) * 2;
            smf[row * 132 + col]           = acc[tm][tn][0];
            smf[row * 132 + col + 1]       = acc[tm][tn][1];
            smf[(row + 8) * 132 + col]     = acc[tm][tn][2];
            smf[(row + 8) * 132 + col + 1] = acc[tm][tn][3];
        }
    __syncthreads();

    // --- fused sLSTM epilogue: thread -> (16 rows, 1 hidden col) ---
    const int jj = t & 31;
    const int rb = (t >> 5) * 16;
    const int jcol = nt * 32 + jj;
    const float b_i = bias[jcol];
    const float b_f = bias[HDIM + jcol];
    const float b_z = bias[2 * HDIM + jcol];
    const float b_o = bias[3 * HDIM + jcol];
    const size_t BH = (size_t)BATCH * HDIM;

    #pragma unroll
    for (int rr = 0; rr < 16; rr++) {
        const int row = rb + rr;
        const size_t idx = (size_t)(mt * 128 + row) * HDIM + jcol;
        const float iv = smf[row * 132 + 0 * 32 + jj] + b_i;
        const float fv = smf[row * 132 + 1 * 32 + jj] + b_f;
        const float zv = smf[row * 132 + 2 * 32 + jj] + b_z;
        const float ov = smf[row * 132 + 3 * 32 + jj] + b_o;
        const float mo = m_in[idx];
        const float mn = fmaxf(fv + mo, iv);
        const float fg = __expf(fv + mo - mn);
        const float ig = __expf(iv - mn);
        const float zg = tanhf(zv);
        const float og = 1.0f / (1.0f + __expf(-ov));
        const float cn = fg * c_in[idx] + ig * zg;
        const float nn = fg * n_in[idx] + ig;
        const float hn = og * (cn / fmaxf(fabsf(nn), 1.0f));
        out[idx]          = hn;
        out[BH + idx]     = cn;
        out[2 * BH + idx] = nn;
        out[3 * BH + idx] = mn;
    }
}

// ================================ launch ====================================
extern "C" void kernel_launch(void* const* d_in, const int* in_sizes, int n_in,
                              void* d_out, int out_size) {
    const float* x    = (const float*)d_in[0];
    const float* h    = (const float*)d_in[1];
    const float* c    = (const float*)d_in[2];
    const float* n    = (const float*)d_in[3];
    const float* m    = (const float*)d_in[4];
    const float* Wx   = (const float*)d_in[5];
    const float* Wh   = (const float*)d_in[6];
    const float* bias = (const float*)d_in[7];
    float* out = (float*)d_out;

    pack_kernel<<<10240, 128>>>(x, h, Wx, Wh);

    cudaFuncSetAttribute(slstm_main, cudaFuncAttributeMaxDynamicSharedMemorySize,
                         SMEM_TOTAL);
    dim3 grid(32, 128);   // (nt, mt)
    slstm_main<<<grid, 256, SMEM_TOTAL>>>(c, n, m, bias, out);
}

// round 11
// speedup vs baseline: 13.0775x; 1.0066x over previous
#include <cuda_runtime.h>
#include <cuda_fp16.h>
#include <cstdint>
#include <math.h>

// ============================================================================
// sLSTM cell: gates = [x|h] @ [Wx|Wh]^T + b, exp-gate epilogue.
// R11: single-pass fp16 GEMM, 3 pair-slot pipeline (1 sync / 2 ktiles), PLUS
//      ks-level fragment double-buffering: LDSM batch for step i+1 issues
//      under step i's MMAs (3 of 4 batches hidden per pair).
// ============================================================================

#define BATCH 16384
#define HDIM  1024
#define NKT   64                         // 64 k-tiles of 32 over K=2048
#define APLANE 8192                      // one 128-row x 32-k fp16 plane
#define STAGE_BYTES (2 * APLANE)         // A | W = 16384
#define STAGES 6
#define SMEM_TOTAL (STAGES * STAGE_BYTES)    // 98304 -> 2 CTAs/SM

__device__ __align__(16) __half g_Apack[(size_t)8192 * 4096]; // 67 MB
__device__ __align__(16) __half g_Wpack[(size_t)2048 * 4096]; // 17 MB

__device__ __forceinline__ uint32_t smem_u32(const void* p) {
    uint32_t a;
    asm("{ .reg .u64 t; cvta.to.shared.u64 t, %1; cvt.u32.u64 %0, t; }" : "=r"(a) : "l"(p));
    return a;
}

#define LDSM_X4(r, addr)                                                        \
    asm volatile("ldmatrix.sync.aligned.m8n8.x4.shared.b16 {%0,%1,%2,%3}, [%4];" \
                 : "=r"((r)[0]), "=r"((r)[1]), "=r"((r)[2]), "=r"((r)[3])       \
                 : "r"(addr))

#define MMA16816(d, a, b)                                                       \
    asm volatile("mma.sync.aligned.m16n8k16.row.col.f32.f16.f16.f32 "           \
                 "{%0,%1,%2,%3}, {%4,%5,%6,%7}, {%8,%9}, {%0,%1,%2,%3};"        \
                 : "+f"((d)[0]), "+f"((d)[1]), "+f"((d)[2]), "+f"((d)[3])       \
                 : "r"((a)[0]), "r"((a)[1]), "r"((a)[2]), "r"((a)[3]),          \
                   "r"((b)[0]), "r"((b)[1]))

#define CP_ASYNC16(dst, src) \
    asm volatile("cp.async.cg.shared.global [%0], [%1], 16;" :: "r"(dst), "l"(src))
#define CP_COMMIT() asm volatile("cp.async.commit_group;" ::: "memory")
#define CP_WAIT1()  asm volatile("cp.async.wait_group 1;" ::: "memory")
#define CP_WAIT0()  asm volatile("cp.async.wait_group 0;" ::: "memory")

__device__ __forceinline__ uint32_t swz(int row, int ch) {
    return (uint32_t)(row * 64 + ((ch ^ ((row >> 1) & 3)) << 4));
}

// ============================== pack kernel =================================
__global__ __launch_bounds__(128) void pack_kernel(
    const float* __restrict__ x, const float* __restrict__ h,
    const float* __restrict__ Wx, const float* __restrict__ Wh)
{
    const int bt = blockIdx.x, t = threadIdx.x;
    const bool isA = bt < 8192;
    const int tile = isA ? bt : bt - 8192;
    const int kt = tile & 63;
    const int rt = tile >> 6;
    const float* src = (kt < 32) ? (isA ? x : Wx) : (isA ? h : Wh);
    const int kbase = (kt & 31) * 32;
    __half* dst = (isA ? g_Apack : g_Wpack) + (size_t)tile * 4096;

    #pragma unroll
    for (int i = 0; i < 8; i++) {
        const int cc = i * 128 + t;
        const int r = cc >> 3, k4 = cc & 7;
        const int grow = isA ? (rt * 128 + r)
                             : ((r >> 5) * HDIM + rt * 32 + (r & 31));
        float4 v = *(const float4*)(src + (size_t)grow * 1024 + kbase + k4 * 4);
        __half2 p0 = __floats2half2_rn(v.x, v.y);
        __half2 p1 = __floats2half2_rn(v.z, v.w);
        *(uint2*)(dst + r * 32 + k4 * 4) =
            make_uint2(*(uint32_t*)&p0, *(uint32_t*)&p1);
    }
}

// =============================== main kernel ================================
// 256 threads = 8 warps in 4(m) x 2(n) grid; warp (wm, wn) computes 32 x 64.
__global__ __launch_bounds__(256, 2) void slstm_main(
    const float* __restrict__ c_in, const float* __restrict__ n_in,
    const float* __restrict__ m_in, const float* __restrict__ bias,
    float* __restrict__ out)
{
    extern __shared__ char smraw[];
    const uint32_t sb = smem_u32(smraw);
    const int t = threadIdx.x, lane = t & 31, wid = t >> 5;
    const int nt = blockIdx.x, mt = blockIdx.y;
    const int wm = wid >> 1, wn = wid & 1;

    const char* Abase = (const char*)g_Apack + (size_t)(mt * 64) * 8192;
    const char* Wbase = (const char*)g_Wpack + (size_t)(nt * 64) * 8192;

    // per-thread LDSM offsets within a plane, for ks=0 (ks=1 adds swz ch+2:
    // ch^2 toggles bit5 of the byte offset -> addr ^ 32)
    uint32_t aoff[2], woff[4];
    #pragma unroll
    for (int tm = 0; tm < 2; tm++) {
        const int r = wm * 32 + tm * 16 + (lane & 15);
        aoff[tm] = swz(r, lane >> 4);
    }
    #pragma unroll
    for (int p = 0; p < 4; p++) {
        const int r = wn * 64 + p * 16 + ((lane >> 4) << 3) + (lane & 7);
        woff[p] = swz(r, (lane >> 3) & 1);
    }

    auto load_stage = [&](int s, int kt) {
        const uint32_t d0 = sb + s * STAGE_BYTES;
        #pragma unroll
        for (int i = 0; i < 4; i++) {
            const int c = i * 256 + t;
            const int plane = c >> 9, w = c & 511;
            const int row = w >> 2, ch = w & 3;
            const char* src = (plane == 0)
                ? Abase + (size_t)kt * 8192 + w * 16
                : Wbase + (size_t)kt * 8192 + w * 16;
            CP_ASYNC16(d0 + plane * APLANE + swz(row, ch), src);
        }
    };

    float acc[2][8][4];
    #pragma unroll
    for (int a = 0; a < 2; a++)
        #pragma unroll
        for (int b = 0; b < 8; b++)
            #pragma unroll
            for (int e = 0; e < 4; e++) acc[a][b][e] = 0.0f;

    // double-buffered fragments
    uint32_t afr[2][2][4], wfr[2][4][4];

    auto load_frags = [&](int buf, uint32_t st, int ks) {
        const uint32_t kx = ks ? 32u : 0u;   // swz ch^2 == byte-offset ^ 32
        #pragma unroll
        for (int tm = 0; tm < 2; tm++)
            LDSM_X4(afr[buf][tm], st + (aoff[tm] ^ kx));
        const uint32_t wst = st + APLANE;
        #pragma unroll
        for (int p = 0; p < 4; p++)
            LDSM_X4(wfr[buf][p], wst + (woff[p] ^ kx));
    };
    auto mma_frags = [&](int buf) {
        #pragma unroll
        for (int tm = 0; tm < 2; tm++)
            #pragma unroll
            for (int tn = 0; tn < 8; tn++)
                MMA16816(acc[tm][tn], afr[buf][tm],
                         (&wfr[buf][tn >> 1][(tn & 1) * 2]));
    };

    // prologue: pairs 0 and 1, one commit group per pair
    load_stage(0, 0); load_stage(1, 1); CP_COMMIT();
    load_stage(2, 2); load_stage(3, 3); CP_COMMIT();

    // main loop: one pair (2 stages, 4 ks-steps) per iteration, 1 sync each.
    for (int kt = 0; kt < NKT; kt += 2) {
        if (kt + 2 >= NKT) { CP_WAIT0(); } else { CP_WAIT1(); }
        __syncthreads();
        if (kt + 4 < NKT) {
            const int slot = ((kt + 4) >> 1) % 3;
            load_stage(2 * slot,     kt + 4);
            load_stage(2 * slot + 1, kt + 5);
            CP_COMMIT();
        }
        const int cslot = (kt >> 1) % 3;
        const uint32_t stA = sb + 2 * cslot * STAGE_BYTES;
        const uint32_t stB = stA + STAGE_BYTES;
        // software-pipelined 4 ks-steps: next LDSM batch under current MMAs
        load_frags(0, stA, 0);
        load_frags(1, stA, 1);  mma_frags(0);
        load_frags(0, stB, 0);  mma_frags(1);
        load_frags(1, stB, 1);  mma_frags(0);
        mma_frags(1);
    }

    // --- exchange accumulators through smem: [128][132] fp32 ---
    __syncthreads();
    float* smf = (float*)smraw;
    #pragma unroll
    for (int tm = 0; tm < 2; tm++)
        #pragma unroll
        for (int tn = 0; tn < 8; tn++) {
            const int row = wm * 32 + tm * 16 + (lane >> 2);
            const int col = wn * 64 + tn * 8 + (lane & 3) * 2;
            smf[row * 132 + col]           = acc[tm][tn][0];
            smf[row * 132 + col + 1]       = acc[tm][tn][1];
            smf[(row + 8) * 132 + col]     = acc[tm][tn][2];
            smf[(row + 8) * 132 + col + 1] = acc[tm][tn][3];
        }
    __syncthreads();

    // --- fused sLSTM epilogue: thread -> (16 rows, 1 hidden col) ---
    const int jj = t & 31;
    const int rb = (t >> 5) * 16;
    const int jcol = nt * 32 + jj;
    const float b_i = bias[jcol];
    const float b_f = bias[HDIM + jcol];
    const float b_z = bias[2 * HDIM + jcol];
    const float b_o = bias[3 * HDIM + jcol];
    const size_t BH = (size_t)BATCH * HDIM;

    #pragma unroll
    for (int rr = 0; rr < 16; rr++) {
        const int row = rb + rr;
        const size_t idx = (size_t)(mt * 128 + row) * HDIM + jcol;
        const float iv = smf[row * 132 + 0 * 32 + jj] + b_i;
        const float fv = smf[row * 132 + 1 * 32 + jj] + b_f;
        const float zv = smf[row * 132 + 2 * 32 + jj] + b_z;
        const float ov = smf[row * 132 + 3 * 32 + jj] + b_o;
        const float mo = m_in[idx];
        const float mn = fmaxf(fv + mo, iv);
        const float fg = __expf(fv + mo - mn);
        const float ig = __expf(iv - mn);
        const float zg = tanhf(zv);
        const float og = 1.0f / (1.0f + __expf(-ov));
        const float cn = fg * c_in[idx] + ig * zg;
        const float nn = fg * n_in[idx] + ig;
        const float hn = og * (cn / fmaxf(fabsf(nn), 1.0f));
        out[idx]          = hn;
        out[BH + idx]     = cn;
        out[2 * BH + idx] = nn;
        out[3 * BH + idx] = mn;
    }
}

// ================================ launch ====================================
extern "C" void kernel_launch(void* const* d_in, const int* in_sizes, int n_in,
                              void* d_out, int out_size) {
    const float* x    = (const float*)d_in[0];
    const float* h    = (const float*)d_in[1];
    const float* c    = (const float*)d_in[2];
    const float* n    = (const float*)d_in[3];
    const float* m    = (const float*)d_in[4];
    const float* Wx   = (const float*)d_in[5];
    const float* Wh   = (const float*)d_in[6];
    const float* bias = (const float*)d_in[7];
    float* out = (float*)d_out;

    pack_kernel<<<10240, 128>>>(x, h, Wx, Wh);

    cudaFuncSetAttribute(slstm_main, cudaFuncAttributeMaxDynamicSharedMemorySize,
                         SMEM_TOTAL);
    dim3 grid(32, 128);   // (nt, mt)
    slstm_main<<<grid, 256, SMEM_TOTAL>>>(c, n, m, bias, out);
}

// round 12
// speedup vs baseline: 14.8562x; 1.1360x over previous
#include <cuda_runtime.h>
#include <cuda_fp16.h>
#include <cstdint>
#include <math.h>

// ============================================================================
// sLSTM cell: gates = [x|h] @ [Wx|Wh]^T + b, exp-gate epilogue.
// R12: mainloop identical to R11 (at HMMA floor). Epilogue reworked:
//      cp.async prefetch of c/n/m into freed pipeline smem (latency hidden
//      under accumulator exchange), two-half exchange, float4 loads/stores.
// ============================================================================

#define BATCH 16384
#define HDIM  1024
#define NKT   64
#define APLANE 8192
#define STAGE_BYTES (2 * APLANE)         // A | W = 16384
#define STAGES 6
#define SMEM_TOTAL (STAGES * STAGE_BYTES)    // 98304 -> 2 CTAs/SM

#define XCHG_BYTES (64 * 132 * 4)        // 33792: half-tile fp32 exchange
#define PRE_OFF    XCHG_BYTES            // c/n/m prefetch: 3 x 16KB

__device__ __align__(16) __half g_Apack[(size_t)8192 * 4096]; // 67 MB
__device__ __align__(16) __half g_Wpack[(size_t)2048 * 4096]; // 17 MB

__device__ __forceinline__ uint32_t smem_u32(const void* p) {
    uint32_t a;
    asm("{ .reg .u64 t; cvta.to.shared.u64 t, %1; cvt.u32.u64 %0, t; }" : "=r"(a) : "l"(p));
    return a;
}

#define LDSM_X4(r, addr)                                                        \
    asm volatile("ldmatrix.sync.aligned.m8n8.x4.shared.b16 {%0,%1,%2,%3}, [%4];" \
                 : "=r"((r)[0]), "=r"((r)[1]), "=r"((r)[2]), "=r"((r)[3])       \
                 : "r"(addr))

#define MMA16816(d, a, b)                                                       \
    asm volatile("mma.sync.aligned.m16n8k16.row.col.f32.f16.f16.f32 "           \
                 "{%0,%1,%2,%3}, {%4,%5,%6,%7}, {%8,%9}, {%0,%1,%2,%3};"        \
                 : "+f"((d)[0]), "+f"((d)[1]), "+f"((d)[2]), "+f"((d)[3])       \
                 : "r"((a)[0]), "r"((a)[1]), "r"((a)[2]), "r"((a)[3]),          \
                   "r"((b)[0]), "r"((b)[1]))

#define CP_ASYNC16(dst, src) \
    asm volatile("cp.async.cg.shared.global [%0], [%1], 16;" :: "r"(dst), "l"(src))
#define CP_COMMIT() asm volatile("cp.async.commit_group;" ::: "memory")
#define CP_WAIT1()  asm volatile("cp.async.wait_group 1;" ::: "memory")
#define CP_WAIT0()  asm volatile("cp.async.wait_group 0;" ::: "memory")

__device__ __forceinline__ uint32_t swz(int row, int ch) {
    return (uint32_t)(row * 64 + ((ch ^ ((row >> 1) & 3)) << 4));
}

// ============================== pack kernel =================================
__global__ __launch_bounds__(128) void pack_kernel(
    const float* __restrict__ x, const float* __restrict__ h,
    const float* __restrict__ Wx, const float* __restrict__ Wh)
{
    const int bt = blockIdx.x, t = threadIdx.x;
    const bool isA = bt < 8192;
    const int tile = isA ? bt : bt - 8192;
    const int kt = tile & 63;
    const int rt = tile >> 6;
    const float* src = (kt < 32) ? (isA ? x : Wx) : (isA ? h : Wh);
    const int kbase = (kt & 31) * 32;
    __half* dst = (isA ? g_Apack : g_Wpack) + (size_t)tile * 4096;

    #pragma unroll
    for (int i = 0; i < 8; i++) {
        const int cc = i * 128 + t;
        const int r = cc >> 3, k4 = cc & 7;
        const int grow = isA ? (rt * 128 + r)
                             : ((r >> 5) * HDIM + rt * 32 + (r & 31));
        float4 v = *(const float4*)(src + (size_t)grow * 1024 + kbase + k4 * 4);
        __half2 p0 = __floats2half2_rn(v.x, v.y);
        __half2 p1 = __floats2half2_rn(v.z, v.w);
        *(uint2*)(dst + r * 32 + k4 * 4) =
            make_uint2(*(uint32_t*)&p0, *(uint32_t*)&p1);
    }
}

// =============================== main kernel ================================
__global__ __launch_bounds__(256, 2) void slstm_main(
    const float* __restrict__ c_in, const float* __restrict__ n_in,
    const float* __restrict__ m_in, const float* __restrict__ bias,
    float* __restrict__ out)
{
    extern __shared__ char smraw[];
    const uint32_t sb = smem_u32(smraw);
    const int t = threadIdx.x, lane = t & 31, wid = t >> 5;
    const int nt = blockIdx.x, mt = blockIdx.y;
    const int wm = wid >> 1, wn = wid & 1;

    const char* Abase = (const char*)g_Apack + (size_t)(mt * 64) * 8192;
    const char* Wbase = (const char*)g_Wpack + (size_t)(nt * 64) * 8192;

    uint32_t aoff[2], woff[4];
    #pragma unroll
    for (int tm = 0; tm < 2; tm++) {
        const int r = wm * 32 + tm * 16 + (lane & 15);
        aoff[tm] = swz(r, lane >> 4);
    }
    #pragma unroll
    for (int p = 0; p < 4; p++) {
        const int r = wn * 64 + p * 16 + ((lane >> 4) << 3) + (lane & 7);
        woff[p] = swz(r, (lane >> 3) & 1);
    }

    auto load_stage = [&](int s, int kt) {
        const uint32_t d0 = sb + s * STAGE_BYTES;
        #pragma unroll
        for (int i = 0; i < 4; i++) {
            const int c = i * 256 + t;
            const int plane = c >> 9, w = c & 511;
            const int row = w >> 2, ch = w & 3;
            const char* src = (plane == 0)
                ? Abase + (size_t)kt * 8192 + w * 16
                : Wbase + (size_t)kt * 8192 + w * 16;
            CP_ASYNC16(d0 + plane * APLANE + swz(row, ch), src);
        }
    };

    float acc[2][8][4];
    #pragma unroll
    for (int a = 0; a < 2; a++)
        #pragma unroll
        for (int b = 0; b < 8; b++)
            #pragma unroll
            for (int e = 0; e < 4; e++) acc[a][b][e] = 0.0f;

    uint32_t afr[2][2][4], wfr[2][4][4];
    auto load_frags = [&](int buf, uint32_t st, int ks) {
        const uint32_t kx = ks ? 32u : 0u;
        #pragma unroll
        for (int tm = 0; tm < 2; tm++)
            LDSM_X4(afr[buf][tm], st + (aoff[tm] ^ kx));
        const uint32_t wst = st + APLANE;
        #pragma unroll
        for (int p = 0; p < 4; p++)
            LDSM_X4(wfr[buf][p], wst + (woff[p] ^ kx));
    };
    auto mma_frags = [&](int buf) {
        #pragma unroll
        for (int tm = 0; tm < 2; tm++)
            #pragma unroll
            for (int tn = 0; tn < 8; tn++)
                MMA16816(acc[tm][tn], afr[buf][tm],
                         (&wfr[buf][tn >> 1][(tn & 1) * 2]));
    };

    load_stage(0, 0); load_stage(1, 1); CP_COMMIT();
    load_stage(2, 2); load_stage(3, 3); CP_COMMIT();

    for (int kt = 0; kt < NKT; kt += 2) {
        if (kt + 2 >= NKT) { CP_WAIT0(); } else { CP_WAIT1(); }
        __syncthreads();
        if (kt + 4 < NKT) {
            const int slot = ((kt + 4) >> 1) % 3;
            load_stage(2 * slot,     kt + 4);
            load_stage(2 * slot + 1, kt + 5);
            CP_COMMIT();
        }
        const int cslot = (kt >> 1) % 3;
        const uint32_t stA = sb + 2 * cslot * STAGE_BYTES;
        const uint32_t stB = stA + STAGE_BYTES;
        load_frags(0, stA, 0);
        load_frags(1, stA, 1);  mma_frags(0);
        load_frags(0, stB, 0);  mma_frags(1);
        load_frags(1, stB, 1);  mma_frags(0);
        mma_frags(1);
    }

    // ===================== epilogue (R12 rework) ============================
    __syncthreads();   // all mainloop smem reads complete

    // 1) prefetch c/n/m tiles (128 rows x 32 cols fp32 each) into PRE region
    {
        const float* srcs[3] = {c_in, n_in, m_in};
        #pragma unroll
        for (int i = 0; i < 12; i++) {
            const int c = i * 256 + t;              // 3072 chunks of 16B
            const int p = c >> 10, w = c & 1023;    // 1024 chunks per array
            const int row = w >> 3, col16 = w & 7;
            const char* src = (const char*)srcs[p]
                + ((size_t)(mt * 128 + row) * HDIM + nt * 32) * 4 + col16 * 16;
            CP_ASYNC16(sb + PRE_OFF + p * 16384 + w * 16, src);
        }
        CP_COMMIT();
    }

    // bias: 4 gates x 4 cols per thread (float4 each)
    const int jc4 = t & 7;                 // float4 col group (0..7)
    const int rp  = t >> 3;                // row pair (0..31)
    const int jj4 = jc4 * 4;
    float4 b4[4];
    #pragma unroll
    for (int g = 0; g < 4; g++)
        b4[g] = *(const float4*)(bias + g * HDIM + nt * 32 + jj4);

    float* smf = (float*)smraw;
    float* pre = (float*)(smraw + PRE_OFF);
    const size_t BH = (size_t)BATCH * HDIM;

    #pragma unroll
    for (int H = 0; H < 2; H++) {
        // exchange: warps owning rows [H*64, H*64+64) write their accs
        if (wm >> 1 == H) {
            #pragma unroll
            for (int tm = 0; tm < 2; tm++)
                #pragma unroll
                for (int tn = 0; tn < 8; tn++) {
                    const int row = (wm & 1) * 32 + tm * 16 + (lane >> 2);
                    const int col = wn * 64 + tn * 8 + (lane & 3) * 2;
                    smf[row * 132 + col]           = acc[tm][tn][0];
                    smf[row * 132 + col + 1]       = acc[tm][tn][1];
                    smf[(row + 8) * 132 + col]     = acc[tm][tn][2];
                    smf[(row + 8) * 132 + col + 1] = acc[tm][tn][3];
                }
        }
        if (H == 0) CP_WAIT0();            // prefetch complete (this thread)
        __syncthreads();                   // exchange + prefetch visible

        // compute: each thread does 2 rows x 4 cols (float4)
        #pragma unroll
        for (int r2 = 0; r2 < 2; r2++) {
            const int rloc = rp * 2 + r2;            // 0..63 within half
            const int grow = mt * 128 + H * 64 + rloc;
            const int prow = H * 64 + rloc;
            float4 c4 = *(float4*)(pre + 0 * 4096 + prow * 32 + jj4);
            float4 n4 = *(float4*)(pre + 1 * 4096 + prow * 32 + jj4);
            float4 m4 = *(float4*)(pre + 2 * 4096 + prow * 32 + jj4);
            float4 ho, co, no, mo4;
            const float* gr = smf + rloc * 132;
            #pragma unroll
            for (int e = 0; e < 4; e++) {
                const float iv = gr[0 * 32 + jj4 + e] + ((const float*)&b4[0])[e];
                const float fv = gr[1 * 32 + jj4 + e] + ((const float*)&b4[1])[e];
                const float zv = gr[2 * 32 + jj4 + e] + ((const float*)&b4[2])[e];
                const float ov = gr[3 * 32 + jj4 + e] + ((const float*)&b4[3])[e];
                const float cv = ((const float*)&c4)[e];
                const float nv = ((const float*)&n4)[e];
                const float mv = ((const float*)&m4)[e];
                const float mn = fmaxf(fv + mv, iv);
                const float fg = __expf(fv + mv - mn);
                const float ig = __expf(iv - mn);
                const float zg = tanhf(zv);
                const float og = 1.0f / (1.0f + __expf(-ov));
                const float cn = fg * cv + ig * zg;
                const float nn = fg * nv + ig;
                const float hn = og * (cn / fmaxf(fabsf(nn), 1.0f));
                ((float*)&ho)[e]  = hn;
                ((float*)&co)[e]  = cn;
                ((float*)&no)[e]  = nn;
                ((float*)&mo4)[e] = mn;
            }
            float* ob = out + (size_t)grow * HDIM + nt * 32 + jj4;
            *(float4*)(ob)           = ho;
            *(float4*)(ob + BH)      = co;
            *(float4*)(ob + 2 * BH)  = no;
            *(float4*)(ob + 3 * BH)  = mo4;
        }
        if (H == 0) __syncthreads();       // half-0 reads done before half-1 writes
    }
}

// ================================ launch ====================================
extern "C" void kernel_launch(void* const* d_in, const int* in_sizes, int n_in,
                              void* d_out, int out_size) {
    const float* x    = (const float*)d_in[0];
    const float* h    = (const float*)d_in[1];
    const float* c    = (const float*)d_in[2];
    const float* n    = (const float*)d_in[3];
    const float* m    = (const float*)d_in[4];
    const float* Wx   = (const float*)d_in[5];
    const float* Wh   = (const float*)d_in[6];
    const float* bias = (const float*)d_in[7];
    float* out = (float*)d_out;

    pack_kernel<<<10240, 128>>>(x, h, Wx, Wh);

    cudaFuncSetAttribute(slstm_main, cudaFuncAttributeMaxDynamicSharedMemorySize,
                         SMEM_TOTAL);
    dim3 grid(32, 128);   // (nt, mt)
    slstm_main<<<grid, 256, SMEM_TOTAL>>>(c, n, m, bias, out);
}